// round 11
// baseline (speedup 1.0000x reference)
#include <cuda_runtime.h>
#include <cuda_fp16.h>
#include <math.h>
#include <stdint.h>

#define NN   96
#define HH   192
#define TPB  320
#define RPT  (10 * 16)   // 10 warps x m16 rows
#define EPSV 1e-6f

// ---------------- smem layout (bytes) ----------------
#define OFF_G     0                       // float gamma[96]
#define OFF_B     384                     // float beta[96]
#define OFF_M     768                     // float m[96]  (column means of D)
#define OFF_B2    1152                    // float b[192] (W1 @ beta)
#define OFF_EHI   1920                    // E' = (W1*gamma)@D - a m^T : 192 x 96, f16 hi
#define STR_E     208
#define SZ_E      (192 * 208)             // 39936
#define OFF_ELO   (OFF_EHI + SZ_E)
#define OFF_W2HI  (OFF_ELO + SZ_E)        // also fp32 D scratch during staging (36864 B)
#define STR_W2    400
#define SZ_W2     (96 * 400)              // 38400
#define OFF_W2LO  (OFF_W2HI + SZ_W2)
#define SMEM_TOTAL (OFF_W2LO + SZ_W2)     // 158592

__device__ __forceinline__ uint32_t smem_u32(const void* p) {
    uint32_t a;
    asm("{ .reg .u64 t; cvta.to.shared.u64 t, %1; cvt.u32.u64 %0, t; }" : "=r"(a) : "l"(p));
    return a;
}

#define LDSM4(d0, d1, d2, d3, a) \
    asm volatile("ldmatrix.sync.aligned.m8n8.x4.shared.b16 {%0,%1,%2,%3}, [%4];" \
        : "=r"(d0), "=r"(d1), "=r"(d2), "=r"(d3) : "r"(a))

#define MMA(ac, A, b0, b1) \
    asm volatile("mma.sync.aligned.m16n8k16.row.col.f32.f16.f16.f32 " \
        "{%0,%1,%2,%3}, {%4,%5,%6,%7}, {%8,%9}, {%0,%1,%2,%3};" \
        : "+f"((ac)[0]), "+f"((ac)[1]), "+f"((ac)[2]), "+f"((ac)[3]) \
        : "r"((A)[0]), "r"((A)[1]), "r"((A)[2]), "r"((A)[3]), "r"(b0), "r"(b1))

__device__ __forceinline__ void sp2(float a, float b, uint32_t& hi, uint32_t& lo) {
    __half2 h = __floats2half2_rn(a, b);
    float ra = a - __low2float(h);
    float rb = b - __high2float(h);
    __half2 l = __floats2half2_rn(ra, rb);
    hi = *(uint32_t*)&h;
    lo = *(uint32_t*)&l;
}

__device__ __forceinline__ float fast_sigmoid(float v) {
    float t;
    asm("tanh.approx.f32 %0, %1;" : "=f"(t) : "f"(v * 0.5f));
    return fmaf(t, 0.5f, 0.5f);
}

extern __shared__ char sm[];

__global__ void __launch_bounds__(TPB, 1)
fused_mma_kernel(const float* __restrict__ x,
                 const float* __restrict__ W1,
                 const float* __restrict__ W2,
                 const float* __restrict__ gamma,
                 const float* __restrict__ beta,
                 float* __restrict__ out,
                 int rows) {
    const int tid  = threadIdx.x;
    const int lane = tid & 31;
    const int warp = tid >> 5;
    const int gid  = lane >> 2;
    const int tig  = lane & 3;
    const uint32_t sb = smem_u32(sm);

    float* sg  = (float*)(sm + OFF_G);
    float* sbt = (float*)(sm + OFF_B);
    float* smv = (float*)(sm + OFF_M);
    float* sb2 = (float*)(sm + OFF_B2);
    float* D32 = (float*)(sm + OFF_W2HI);   // staging scratch

    // ========== STAGE 1: gamma/beta + fp32 DCT matrix into scratch ==========
    if (tid < 96) { sg[tid] = gamma[tid]; sbt[tid] = beta[tid]; }
    const float PI192 = 0.016362461737446838f;
    for (int t = tid; t < 96 * 96; t += TPB) {
        int k = t / 96, i = t % 96;
        int mm = ((2 * i + 1) * k) % 384;
        D32[t] = 2.0f * cosf(PI192 * (float)mm);
    }
    __syncthreads();

    // ========== STAGE 2: m (col means of D), b = W1@beta ==========
    if (tid < 96) {
        float s = 0.f;
        for (int k = 0; k < 96; k++) s += D32[k * 96 + tid];
        smv[tid] = s * (1.0f / 96.0f);
    }
    if (tid < 192) {
        float bbv = 0.f;
        for (int k = 0; k < 96; k++) bbv = fmaf(W1[tid * 96 + k], sbt[k], bbv);
        sb2[tid] = bbv;
    }
    __syncthreads();

    // ========== STAGE 3: E' = (W1*gamma)@D - a m^T (f16 split) ==========
    // 256 threads: each does 6 E-rows x 12 cols (32 n-blocks x 8 i-blocks)
    if (tid < 256) {
        int bn = (tid >> 3) * 6;       // n-block 0..186
        int bi = (tid & 7) * 12;       // i-block 0..84
        float ea[6][12];
        float aa[6] = {0.f, 0.f, 0.f, 0.f, 0.f, 0.f};
#pragma unroll
        for (int n2 = 0; n2 < 6; n2++)
#pragma unroll
            for (int ii = 0; ii < 12; ii++) ea[n2][ii] = 0.f;
        for (int k = 0; k < 96; k++) {
            float gk = sg[k];
            float wv[6];
#pragma unroll
            for (int n2 = 0; n2 < 6; n2++) {
                wv[n2] = W1[(bn + n2) * 96 + k] * gk;
                aa[n2] += wv[n2];
            }
#pragma unroll
            for (int ii = 0; ii < 12; ii += 2) {
                float2 dv = *(float2*)(D32 + k * 96 + bi + ii);
#pragma unroll
                for (int n2 = 0; n2 < 6; n2++) {
                    ea[n2][ii]     = fmaf(wv[n2], dv.x, ea[n2][ii]);
                    ea[n2][ii + 1] = fmaf(wv[n2], dv.y, ea[n2][ii + 1]);
                }
            }
        }
#pragma unroll
        for (int n2 = 0; n2 < 6; n2++)
#pragma unroll
            for (int ii = 0; ii < 12; ii++) {
                float v = ea[n2][ii] - aa[n2] * smv[bi + ii];   // fold -a m^T
                __half h = __float2half_rn(v);
                __half l = __float2half_rn(v - __half2float(h));
                int off = (bn + n2) * STR_E + (bi + ii) * 2;
                *(__half*)(sm + OFF_EHI + off) = h;
                *(__half*)(sm + OFF_ELO + off) = l;
            }
    }
    __syncthreads();

    // ========== STAGE 4: W2 f16 split (overwrites D scratch) ==========
    for (int t = tid; t < 96 * 192; t += TPB) {
        int n = t / 192, i = t % 192;
        float v = W2[t];
        __half h = __float2half_rn(v);
        __half l = __float2half_rn(v - __half2float(h));
        *(__half*)(sm + OFF_W2HI + n * STR_W2 + i * 2) = h;
        *(__half*)(sm + OFF_W2LO + n * STR_W2 + i * 2) = l;
    }
    __syncthreads();

    const uint32_t lrow = lane & 7;
    const uint32_t lkb  = (uint32_t)(lane >> 3) * 16;
    const uint32_t bEh  = sb + OFF_EHI  + lrow * STR_E  + lkb;
    const uint32_t bEl  = sb + OFF_ELO  + lrow * STR_E  + lkb;
    const uint32_t bW2h = sb + OFF_W2HI + lrow * STR_W2 + lkb;
    const uint32_t bW2l = sb + OFF_W2LO + lrow * STR_W2 + lkb;

    const int ntiles = (rows + RPT - 1) / RPT;

    for (int tile = blockIdx.x; tile < ntiles; tile += gridDim.x) {
        const int r0 = tile * RPT + warp * 16 + gid;
        const int r1 = r0 + 8;
        const float* xr0 = x + (size_t)min(r0, rows - 1) * NN;
        const float* xr1 = x + (size_t)min(r1, rows - 1) * NN;

        // ===== load x, build split A-fragments, accumulate LN1 stats from x =====
        uint32_t a2h[6][4], a2l[6][4];
        float s1_0 = 0.f, sq_0 = 0.f, sm_0 = 0.f;
        float s1_1 = 0.f, sq_1 = 0.f, sm_1 = 0.f;
#pragma unroll
        for (int ktp = 0; ktp < 3; ktp++) {
            int kb = 32 * ktp + 2 * tig;
#pragma unroll
            for (int p = 0; p < 4; p++) {
                float2 v0 = *(const float2*)(xr0 + kb + 8 * p);
                float2 v1 = *(const float2*)(xr1 + kb + 8 * p);
                float2 mv = *(const float2*)(smv + kb + 8 * p);
                s1_0 += v0.x + v0.y;
                sq_0 = fmaf(v0.x, v0.x, fmaf(v0.y, v0.y, sq_0));
                sm_0 = fmaf(v0.x, mv.x, fmaf(v0.y, mv.y, sm_0));
                s1_1 += v1.x + v1.y;
                sq_1 = fmaf(v1.x, v1.x, fmaf(v1.y, v1.y, sq_1));
                sm_1 = fmaf(v1.x, mv.x, fmaf(v1.y, mv.y, sm_1));
                int kk = 2 * ktp + (p >> 1);
                int of = (p & 1) * 2;
                sp2(v0.x, v0.y, a2h[kk][of],     a2l[kk][of]);
                sp2(v1.x, v1.y, a2h[kk][of + 1], a2l[kk][of + 1]);
            }
        }
        s1_0 += __shfl_xor_sync(~0u, s1_0, 1); s1_0 += __shfl_xor_sync(~0u, s1_0, 2);
        sq_0 += __shfl_xor_sync(~0u, sq_0, 1); sq_0 += __shfl_xor_sync(~0u, sq_0, 2);
        sm_0 += __shfl_xor_sync(~0u, sm_0, 1); sm_0 += __shfl_xor_sync(~0u, sm_0, 2);
        s1_1 += __shfl_xor_sync(~0u, s1_1, 1); s1_1 += __shfl_xor_sync(~0u, s1_1, 2);
        sq_1 += __shfl_xor_sync(~0u, sq_1, 1); sq_1 += __shfl_xor_sync(~0u, sq_1, 2);
        sm_1 += __shfl_xor_sync(~0u, sm_1, 1); sm_1 += __shfl_xor_sync(~0u, sm_1, 2);
        // LN1 via DCT row structure: sum(y^2) = 192*||x||^2 + 2*(sum x)^2 ; mu = x.m
        float var0 = 2.0f * sq_0 + s1_0 * s1_0 * (1.0f / 48.0f) - sm_0 * sm_0;
        float var1 = 2.0f * sq_1 + s1_1 * s1_1 * (1.0f / 48.0f) - sm_1 * sm_1;
        float rs0 = rsqrtf(var0 + EPSV);
        float rs1 = rsqrtf(var1 + EPSV);

        // ========== Fused GEMM-E' (x@E'^T -> rs*z+b -> relu) -> GEMM3 ==========
        float sfr[12][4];
#pragma unroll
        for (int i = 0; i < 12; i++) { sfr[i][0] = sfr[i][1] = sfr[i][2] = sfr[i][3] = 0.f; }

#pragma unroll
        for (int g = 0; g < 6; g++) {
            float ac2[4][4];
#pragma unroll
            for (int j = 0; j < 4; j++) { ac2[j][0] = ac2[j][1] = ac2[j][2] = ac2[j][3] = 0.f; }
#pragma unroll
            for (int ktp = 0; ktp < 3; ktp++) {
                uint32_t wh[4][4], wl[4][4];
#pragma unroll
                for (int j = 0; j < 4; j++) {
                    int nt = 4 * g + j;
                    LDSM4(wh[j][0], wh[j][1], wh[j][2], wh[j][3], bEh + nt * (8 * STR_E) + ktp * 64);
                    LDSM4(wl[j][0], wl[j][1], wl[j][2], wl[j][3], bEl + nt * (8 * STR_E) + ktp * 64);
                }
#pragma unroll
                for (int j = 0; j < 4; j++) MMA(ac2[j], a2h[2*ktp],     wh[j][0], wh[j][1]);
#pragma unroll
                for (int j = 0; j < 4; j++) MMA(ac2[j], a2h[2*ktp],     wl[j][0], wl[j][1]);
#pragma unroll
                for (int j = 0; j < 4; j++) MMA(ac2[j], a2l[2*ktp],     wh[j][0], wh[j][1]);
#pragma unroll
                for (int j = 0; j < 4; j++) MMA(ac2[j], a2h[2*ktp + 1], wh[j][2], wh[j][3]);
#pragma unroll
                for (int j = 0; j < 4; j++) MMA(ac2[j], a2h[2*ktp + 1], wl[j][2], wl[j][3]);
#pragma unroll
                for (int j = 0; j < 4; j++) MMA(ac2[j], a2l[2*ktp + 1], wh[j][2], wh[j][3]);
            }
            // rs*z + b, relu, pack -> GEMM3 k32 A-fragments
            uint32_t h0h[4], h0l[4], h1h[4], h1l[4];
#pragma unroll
            for (int j = 0; j < 4; j++) {
                int nt = 4 * g + j;
                float2 bv = *(const float2*)(sb2 + 8 * nt + 2 * tig);
                float e0 = fmaxf(fmaf(rs0, ac2[j][0], bv.x), 0.f);
                float e1 = fmaxf(fmaf(rs0, ac2[j][1], bv.y), 0.f);
                float e2 = fmaxf(fmaf(rs1, ac2[j][2], bv.x), 0.f);
                float e3 = fmaxf(fmaf(rs1, ac2[j][3], bv.y), 0.f);
                if (j < 2) {
                    sp2(e0, e1, h0h[2 * j],     h0l[2 * j]);
                    sp2(e2, e3, h0h[2 * j + 1], h0l[2 * j + 1]);
                } else {
                    sp2(e0, e1, h1h[2 * (j - 2)],     h1l[2 * (j - 2)]);
                    sp2(e2, e3, h1h[2 * (j - 2) + 1], h1l[2 * (j - 2) + 1]);
                }
            }

            // GEMM3 k32 update, n-tiles batched in groups of 4
#pragma unroll
            for (int jb = 0; jb < 3; jb++) {
                uint32_t vh[4][4], vl[4][4];
#pragma unroll
                for (int j = 0; j < 4; j++) {
                    int nt = 4 * jb + j;
                    LDSM4(vh[j][0], vh[j][1], vh[j][2], vh[j][3], bW2h + nt * (8 * STR_W2) + g * 64);
                    LDSM4(vl[j][0], vl[j][1], vl[j][2], vl[j][3], bW2l + nt * (8 * STR_W2) + g * 64);
                }
#pragma unroll
                for (int j = 0; j < 4; j++) MMA(sfr[4*jb+j], h0h, vh[j][0], vh[j][1]);
#pragma unroll
                for (int j = 0; j < 4; j++) MMA(sfr[4*jb+j], h0h, vl[j][0], vl[j][1]);
#pragma unroll
                for (int j = 0; j < 4; j++) MMA(sfr[4*jb+j], h0l, vh[j][0], vh[j][1]);
#pragma unroll
                for (int j = 0; j < 4; j++) MMA(sfr[4*jb+j], h1h, vh[j][2], vh[j][3]);
#pragma unroll
                for (int j = 0; j < 4; j++) MMA(sfr[4*jb+j], h1h, vl[j][2], vl[j][3]);
#pragma unroll
                for (int j = 0; j < 4; j++) MMA(sfr[4*jb+j], h1l, vh[j][2], vh[j][3]);
            }
        }

        // ================= sigmoid + LayerNorm 2 + output =================
#pragma unroll
        for (int nt = 0; nt < 12; nt++)
#pragma unroll
            for (int q = 0; q < 4; q++)
                sfr[nt][q] = fast_sigmoid(sfr[nt][q]);

        float t0 = 0.f, t1 = 0.f;
#pragma unroll
        for (int nt = 0; nt < 12; nt++) { t0 += sfr[nt][0] + sfr[nt][1]; t1 += sfr[nt][2] + sfr[nt][3]; }
        t0 += __shfl_xor_sync(~0u, t0, 1); t0 += __shfl_xor_sync(~0u, t0, 2);
        t1 += __shfl_xor_sync(~0u, t1, 1); t1 += __shfl_xor_sync(~0u, t1, 2);
        float m20 = t0 * (1.f/96.f), m21 = t1 * (1.f/96.f);
        float p0 = 0.f, p1 = 0.f;
#pragma unroll
        for (int nt = 0; nt < 12; nt++) {
            float d;
            d = sfr[nt][0] - m20; p0 = fmaf(d, d, p0);
            d = sfr[nt][1] - m20; p0 = fmaf(d, d, p0);
            d = sfr[nt][2] - m21; p1 = fmaf(d, d, p1);
            d = sfr[nt][3] - m21; p1 = fmaf(d, d, p1);
        }
        p0 += __shfl_xor_sync(~0u, p0, 1); p0 += __shfl_xor_sync(~0u, p0, 2);
        p1 += __shfl_xor_sync(~0u, p1, 1); p1 += __shfl_xor_sync(~0u, p1, 2);
        float rz0 = rsqrtf(p0 * (1.f/96.f) + EPSV);
        float rz1 = rsqrtf(p1 * (1.f/96.f) + EPSV);

#pragma unroll
        for (int nt = 0; nt < 12; nt++) {
            int col = 8 * nt + 2 * tig;
            float2 gv = *(const float2*)(sg  + col);
            float2 bv = *(const float2*)(sbt + col);
            float w00 = fmaf((sfr[nt][0] - m20) * rz0, gv.x, bv.x);
            float w01 = fmaf((sfr[nt][1] - m20) * rz0, gv.y, bv.y);
            float w10 = fmaf((sfr[nt][2] - m21) * rz1, gv.x, bv.x);
            float w11 = fmaf((sfr[nt][3] - m21) * rz1, gv.y, bv.y);
            if (r0 < rows) {
                float2 xv = *(const float2*)(x + (size_t)r0 * NN + col);
                float2 o; o.x = xv.x * w00; o.y = xv.y * w01;
                *(float2*)(out + (size_t)r0 * NN + col) = o;
            }
            if (r1 < rows) {
                float2 xv = *(const float2*)(x + (size_t)r1 * NN + col);
                float2 o; o.x = xv.x * w10; o.y = xv.y * w11;
                *(float2*)(out + (size_t)r1 * NN + col) = o;
            }
        }
    }
}

extern "C" void kernel_launch(void* const* d_in, const int* in_sizes, int n_in,
                              void* d_out, int out_size) {
    const float* x     = (const float*)d_in[0];
    const float* W1    = (const float*)d_in[1];
    const float* W2    = (const float*)d_in[2];
    const float* gamma = (const float*)d_in[3];
    const float* beta  = (const float*)d_in[4];
    float* out = (float*)d_out;

    int rows = in_sizes[0] / NN;

    cudaFuncSetAttribute(fused_mma_kernel, cudaFuncAttributeMaxDynamicSharedMemorySize, SMEM_TOTAL);
    fused_mma_kernel<<<152, TPB, SMEM_TOTAL>>>(x, W1, W2, gamma, beta, out, rows);
}

// round 12
// speedup vs baseline: 1.2536x; 1.2536x over previous
#include <cuda_runtime.h>
#include <cuda_fp16.h>
#include <math.h>
#include <stdint.h>

#define NN   96
#define HH   192
#define TPB  384
#define RPT  (12 * 16)   // 12 warps x m16 rows
#define EPSV 1e-6f

// ---------------- smem layout (bytes) ----------------
#define OFF_G     0                       // float gamma[96]
#define OFF_B     384                     // float beta[96]
#define OFF_M     768                     // float m[96]  (column means of D)
#define OFF_B2    1152                    // float b[192] (W1 @ beta)
#define OFF_EHI   1920                    // E' = (W1*gamma)@D - a m^T : 192 x 96, f16 hi
#define STR_E     208
#define SZ_E      (192 * 208)             // 39936
#define OFF_ELO   (OFF_EHI + SZ_E)
#define OFF_W2HI  (OFF_ELO + SZ_E)        // also fp32 D scratch during staging (36864 B)
#define STR_W2    400
#define SZ_W2     (96 * 400)              // 38400
#define OFF_W2LO  (OFF_W2HI + SZ_W2)
#define SMEM_TOTAL (OFF_W2LO + SZ_W2)     // 158592

__device__ __forceinline__ uint32_t smem_u32(const void* p) {
    uint32_t a;
    asm("{ .reg .u64 t; cvta.to.shared.u64 t, %1; cvt.u32.u64 %0, t; }" : "=r"(a) : "l"(p));
    return a;
}

#define LDSM4(d0, d1, d2, d3, a) \
    asm volatile("ldmatrix.sync.aligned.m8n8.x4.shared.b16 {%0,%1,%2,%3}, [%4];" \
        : "=r"(d0), "=r"(d1), "=r"(d2), "=r"(d3) : "r"(a))

#define MMA(ac, A, b0, b1) \
    asm volatile("mma.sync.aligned.m16n8k16.row.col.f32.f16.f16.f32 " \
        "{%0,%1,%2,%3}, {%4,%5,%6,%7}, {%8,%9}, {%0,%1,%2,%3};" \
        : "+f"((ac)[0]), "+f"((ac)[1]), "+f"((ac)[2]), "+f"((ac)[3]) \
        : "r"((A)[0]), "r"((A)[1]), "r"((A)[2]), "r"((A)[3]), "r"(b0), "r"(b1))

__device__ __forceinline__ void sp2(float a, float b, uint32_t& hi, uint32_t& lo) {
    __half2 h = __floats2half2_rn(a, b);
    float ra = a - __low2float(h);
    float rb = b - __high2float(h);
    __half2 l = __floats2half2_rn(ra, rb);
    hi = *(uint32_t*)&h;
    lo = *(uint32_t*)&l;
}

__device__ __forceinline__ float fast_sigmoid(float v) {
    float t;
    asm("tanh.approx.f32 %0, %1;" : "=f"(t) : "f"(v * 0.5f));
    return fmaf(t, 0.5f, 0.5f);
}

extern __shared__ char sm[];

__global__ void __launch_bounds__(TPB, 1)
fused_mma_kernel(const float* __restrict__ x,
                 const float* __restrict__ W1,
                 const float* __restrict__ W2,
                 const float* __restrict__ gamma,
                 const float* __restrict__ beta,
                 float* __restrict__ out,
                 int rows) {
    const int tid  = threadIdx.x;
    const int lane = tid & 31;
    const int warp = tid >> 5;
    const int gid  = lane >> 2;
    const int tig  = lane & 3;
    const uint32_t sb = smem_u32(sm);

    float* sg  = (float*)(sm + OFF_G);
    float* sbt = (float*)(sm + OFF_B);
    float* smv = (float*)(sm + OFF_M);
    float* sb2 = (float*)(sm + OFF_B2);
    float* D32 = (float*)(sm + OFF_W2HI);   // staging scratch

    // ========== STAGE 1: gamma/beta + fp32 DCT matrix into scratch ==========
    if (tid < 96) { sg[tid] = gamma[tid]; sbt[tid] = beta[tid]; }
    const float PI192 = 0.016362461737446838f;
    for (int t = tid; t < 96 * 96; t += TPB) {
        int k = t / 96, i = t % 96;
        int mm = ((2 * i + 1) * k) % 384;
        D32[t] = 2.0f * cosf(PI192 * (float)mm);
    }
    __syncthreads();

    // ========== STAGE 2: m (col means of D), b = W1@beta ==========
    if (tid < 96) {
        float s = 0.f;
        for (int k = 0; k < 96; k++) s += D32[k * 96 + tid];
        smv[tid] = s * (1.0f / 96.0f);
    }
    if (tid < 192) {
        float bbv = 0.f;
        for (int k = 0; k < 96; k++) bbv = fmaf(W1[tid * 96 + k], sbt[k], bbv);
        sb2[tid] = bbv;
    }
    __syncthreads();

    // ========== STAGE 3: E' = (W1*gamma)@D - a m^T (f16 split) ==========
    {
        int bn = (tid >> 3) * 4;       // n-block 0..188
        int bi = (tid & 7) * 12;       // i-block 0..84
        float ea[4][12];
        float aa[4] = {0.f, 0.f, 0.f, 0.f};
#pragma unroll
        for (int n2 = 0; n2 < 4; n2++)
#pragma unroll
            for (int ii = 0; ii < 12; ii++) ea[n2][ii] = 0.f;
        for (int k = 0; k < 96; k++) {
            float gk = sg[k];
            float w0 = W1[(bn + 0) * 96 + k] * gk;
            float w1 = W1[(bn + 1) * 96 + k] * gk;
            float w2 = W1[(bn + 2) * 96 + k] * gk;
            float w3 = W1[(bn + 3) * 96 + k] * gk;
            aa[0] += w0; aa[1] += w1; aa[2] += w2; aa[3] += w3;
#pragma unroll
            for (int ii = 0; ii < 12; ii += 2) {
                float2 dv = *(float2*)(D32 + k * 96 + bi + ii);
                ea[0][ii] = fmaf(w0, dv.x, ea[0][ii]); ea[0][ii+1] = fmaf(w0, dv.y, ea[0][ii+1]);
                ea[1][ii] = fmaf(w1, dv.x, ea[1][ii]); ea[1][ii+1] = fmaf(w1, dv.y, ea[1][ii+1]);
                ea[2][ii] = fmaf(w2, dv.x, ea[2][ii]); ea[2][ii+1] = fmaf(w2, dv.y, ea[2][ii+1]);
                ea[3][ii] = fmaf(w3, dv.x, ea[3][ii]); ea[3][ii+1] = fmaf(w3, dv.y, ea[3][ii+1]);
            }
        }
#pragma unroll
        for (int n2 = 0; n2 < 4; n2++)
#pragma unroll
            for (int ii = 0; ii < 12; ii++) {
                float v = ea[n2][ii] - aa[n2] * smv[bi + ii];   // fold -a m^T
                __half h = __float2half_rn(v);
                __half l = __float2half_rn(v - __half2float(h));
                int off = (bn + n2) * STR_E + (bi + ii) * 2;
                *(__half*)(sm + OFF_EHI + off) = h;
                *(__half*)(sm + OFF_ELO + off) = l;
            }
    }
    __syncthreads();

    // ========== STAGE 4: W2 f16 split (overwrites D scratch) ==========
    for (int t = tid; t < 96 * 192; t += TPB) {
        int n = t / 192, i = t % 192;
        float v = W2[t];
        __half h = __float2half_rn(v);
        __half l = __float2half_rn(v - __half2float(h));
        *(__half*)(sm + OFF_W2HI + n * STR_W2 + i * 2) = h;
        *(__half*)(sm + OFF_W2LO + n * STR_W2 + i * 2) = l;
    }
    __syncthreads();

    const uint32_t lrow = lane & 7;
    const uint32_t lkb  = (uint32_t)(lane >> 3) * 16;
    const uint32_t bEh  = sb + OFF_EHI  + lrow * STR_E  + lkb;
    const uint32_t bEl  = sb + OFF_ELO  + lrow * STR_E  + lkb;
    const uint32_t bW2h = sb + OFF_W2HI + lrow * STR_W2 + lkb;

    const int ntiles = (rows + RPT - 1) / RPT;

    for (int tile = blockIdx.x; tile < ntiles; tile += gridDim.x) {
        const int r0 = tile * RPT + warp * 16 + gid;
        const int r1 = r0 + 8;
        const float* xr0 = x + (size_t)min(r0, rows - 1) * NN;
        const float* xr1 = x + (size_t)min(r1, rows - 1) * NN;

        // ===== load x, build split A-fragments, accumulate LN1 stats from x =====
        uint32_t a2h[6][4], a2l[6][4];
        float s1_0 = 0.f, sq_0 = 0.f, sm_0 = 0.f;
        float s1_1 = 0.f, sq_1 = 0.f, sm_1 = 0.f;
#pragma unroll
        for (int ktp = 0; ktp < 3; ktp++) {
            int kb = 32 * ktp + 2 * tig;
#pragma unroll
            for (int p = 0; p < 4; p++) {
                float2 v0 = *(const float2*)(xr0 + kb + 8 * p);
                float2 v1 = *(const float2*)(xr1 + kb + 8 * p);
                float2 mv = *(const float2*)(smv + kb + 8 * p);
                s1_0 += v0.x + v0.y;
                sq_0 = fmaf(v0.x, v0.x, fmaf(v0.y, v0.y, sq_0));
                sm_0 = fmaf(v0.x, mv.x, fmaf(v0.y, mv.y, sm_0));
                s1_1 += v1.x + v1.y;
                sq_1 = fmaf(v1.x, v1.x, fmaf(v1.y, v1.y, sq_1));
                sm_1 = fmaf(v1.x, mv.x, fmaf(v1.y, mv.y, sm_1));
                int kk = 2 * ktp + (p >> 1);
                int of = (p & 1) * 2;
                sp2(v0.x, v0.y, a2h[kk][of],     a2l[kk][of]);
                sp2(v1.x, v1.y, a2h[kk][of + 1], a2l[kk][of + 1]);
            }
        }
        s1_0 += __shfl_xor_sync(~0u, s1_0, 1); s1_0 += __shfl_xor_sync(~0u, s1_0, 2);
        sq_0 += __shfl_xor_sync(~0u, sq_0, 1); sq_0 += __shfl_xor_sync(~0u, sq_0, 2);
        sm_0 += __shfl_xor_sync(~0u, sm_0, 1); sm_0 += __shfl_xor_sync(~0u, sm_0, 2);
        s1_1 += __shfl_xor_sync(~0u, s1_1, 1); s1_1 += __shfl_xor_sync(~0u, s1_1, 2);
        sq_1 += __shfl_xor_sync(~0u, sq_1, 1); sq_1 += __shfl_xor_sync(~0u, sq_1, 2);
        sm_1 += __shfl_xor_sync(~0u, sm_1, 1); sm_1 += __shfl_xor_sync(~0u, sm_1, 2);
        // LN1 via DCT row structure: sum(y^2) = 192*||x||^2 + 2*(sum x)^2 ; mu = x.m
        float var0 = 2.0f * sq_0 + s1_0 * s1_0 * (1.0f / 48.0f) - sm_0 * sm_0;
        float var1 = 2.0f * sq_1 + s1_1 * s1_1 * (1.0f / 48.0f) - sm_1 * sm_1;
        float rs0 = rsqrtf(var0 + EPSV);
        float rs1 = rsqrtf(var1 + EPSV);

        // ========== Fused GEMM-E' (x@E'^T -> rs*z+b -> relu) -> GEMM3 ==========
        float sfr[12][4];
#pragma unroll
        for (int i = 0; i < 12; i++) { sfr[i][0] = sfr[i][1] = sfr[i][2] = sfr[i][3] = 0.f; }

#pragma unroll
        for (int g = 0; g < 6; g++) {
            float ac2[4][4];
#pragma unroll
            for (int j = 0; j < 4; j++) { ac2[j][0] = ac2[j][1] = ac2[j][2] = ac2[j][3] = 0.f; }
#pragma unroll
            for (int ktp = 0; ktp < 3; ktp++) {
                uint32_t wh[4][4], wl[4][4];
#pragma unroll
                for (int j = 0; j < 4; j++) {
                    int nt = 4 * g + j;
                    LDSM4(wh[j][0], wh[j][1], wh[j][2], wh[j][3], bEh + nt * (8 * STR_E) + ktp * 64);
                    LDSM4(wl[j][0], wl[j][1], wl[j][2], wl[j][3], bEl + nt * (8 * STR_E) + ktp * 64);
                }
#pragma unroll
                for (int j = 0; j < 4; j++) MMA(ac2[j], a2h[2*ktp],     wh[j][0], wh[j][1]);
#pragma unroll
                for (int j = 0; j < 4; j++) MMA(ac2[j], a2h[2*ktp],     wl[j][0], wl[j][1]);
#pragma unroll
                for (int j = 0; j < 4; j++) MMA(ac2[j], a2l[2*ktp],     wh[j][0], wh[j][1]);
#pragma unroll
                for (int j = 0; j < 4; j++) MMA(ac2[j], a2h[2*ktp + 1], wh[j][2], wh[j][3]);
#pragma unroll
                for (int j = 0; j < 4; j++) MMA(ac2[j], a2h[2*ktp + 1], wl[j][2], wl[j][3]);
#pragma unroll
                for (int j = 0; j < 4; j++) MMA(ac2[j], a2l[2*ktp + 1], wh[j][2], wh[j][3]);
            }
            // rs*z + b, relu, pack -> GEMM3 k32 A-fragments
            uint32_t h0h[4], h0l[4], h1h[4], h1l[4];
#pragma unroll
            for (int j = 0; j < 4; j++) {
                int nt = 4 * g + j;
                float2 bv = *(const float2*)(sb2 + 8 * nt + 2 * tig);
                float e0 = fmaxf(fmaf(rs0, ac2[j][0], bv.x), 0.f);
                float e1 = fmaxf(fmaf(rs0, ac2[j][1], bv.y), 0.f);
                float e2 = fmaxf(fmaf(rs1, ac2[j][2], bv.x), 0.f);
                float e3 = fmaxf(fmaf(rs1, ac2[j][3], bv.y), 0.f);
                if (j < 2) {
                    sp2(e0, e1, h0h[2 * j],     h0l[2 * j]);
                    sp2(e2, e3, h0h[2 * j + 1], h0l[2 * j + 1]);
                } else {
                    sp2(e0, e1, h1h[2 * (j - 2)],     h1l[2 * (j - 2)]);
                    sp2(e2, e3, h1h[2 * (j - 2) + 1], h1l[2 * (j - 2) + 1]);
                }
            }

            // GEMM3 k32 update: W2 hi-only (weight residual dropped), h-residual kept
#pragma unroll
            for (int jb = 0; jb < 3; jb++) {
                uint32_t vh[4][4];
#pragma unroll
                for (int j = 0; j < 4; j++) {
                    int nt = 4 * jb + j;
                    LDSM4(vh[j][0], vh[j][1], vh[j][2], vh[j][3], bW2h + nt * (8 * STR_W2) + g * 64);
                }
#pragma unroll
                for (int j = 0; j < 4; j++) MMA(sfr[4*jb+j], h0h, vh[j][0], vh[j][1]);
#pragma unroll
                for (int j = 0; j < 4; j++) MMA(sfr[4*jb+j], h0l, vh[j][0], vh[j][1]);
#pragma unroll
                for (int j = 0; j < 4; j++) MMA(sfr[4*jb+j], h1h, vh[j][2], vh[j][3]);
#pragma unroll
                for (int j = 0; j < 4; j++) MMA(sfr[4*jb+j], h1l, vh[j][2], vh[j][3]);
            }
        }

        // ================= sigmoid + LayerNorm 2 + output =================
#pragma unroll
        for (int nt = 0; nt < 12; nt++)
#pragma unroll
            for (int q = 0; q < 4; q++)
                sfr[nt][q] = fast_sigmoid(sfr[nt][q]);

        float t0 = 0.f, t1 = 0.f;
#pragma unroll
        for (int nt = 0; nt < 12; nt++) { t0 += sfr[nt][0] + sfr[nt][1]; t1 += sfr[nt][2] + sfr[nt][3]; }
        t0 += __shfl_xor_sync(~0u, t0, 1); t0 += __shfl_xor_sync(~0u, t0, 2);
        t1 += __shfl_xor_sync(~0u, t1, 1); t1 += __shfl_xor_sync(~0u, t1, 2);
        float m20 = t0 * (1.f/96.f), m21 = t1 * (1.f/96.f);
        float p0 = 0.f, p1 = 0.f;
#pragma unroll
        for (int nt = 0; nt < 12; nt++) {
            float d;
            d = sfr[nt][0] - m20; p0 = fmaf(d, d, p0);
            d = sfr[nt][1] - m20; p0 = fmaf(d, d, p0);
            d = sfr[nt][2] - m21; p1 = fmaf(d, d, p1);
            d = sfr[nt][3] - m21; p1 = fmaf(d, d, p1);
        }
        p0 += __shfl_xor_sync(~0u, p0, 1); p0 += __shfl_xor_sync(~0u, p0, 2);
        p1 += __shfl_xor_sync(~0u, p1, 1); p1 += __shfl_xor_sync(~0u, p1, 2);
        float rz0 = rsqrtf(p0 * (1.f/96.f) + EPSV);
        float rz1 = rsqrtf(p1 * (1.f/96.f) + EPSV);

#pragma unroll
        for (int nt = 0; nt < 12; nt++) {
            int col = 8 * nt + 2 * tig;
            float2 gv = *(const float2*)(sg  + col);
            float2 bv = *(const float2*)(sbt + col);
            float w00 = fmaf((sfr[nt][0] - m20) * rz0, gv.x, bv.x);
            float w01 = fmaf((sfr[nt][1] - m20) * rz0, gv.y, bv.y);
            float w10 = fmaf((sfr[nt][2] - m21) * rz1, gv.x, bv.x);
            float w11 = fmaf((sfr[nt][3] - m21) * rz1, gv.y, bv.y);
            if (r0 < rows) {
                float2 xv = *(const float2*)(x + (size_t)r0 * NN + col);
                float2 o; o.x = xv.x * w00; o.y = xv.y * w01;
                *(float2*)(out + (size_t)r0 * NN + col) = o;
            }
            if (r1 < rows) {
                float2 xv = *(const float2*)(x + (size_t)r1 * NN + col);
                float2 o; o.x = xv.x * w10; o.y = xv.y * w11;
                *(float2*)(out + (size_t)r1 * NN + col) = o;
            }
        }
    }
}

extern "C" void kernel_launch(void* const* d_in, const int* in_sizes, int n_in,
                              void* d_out, int out_size) {
    const float* x     = (const float*)d_in[0];
    const float* W1    = (const float*)d_in[1];
    const float* W2    = (const float*)d_in[2];
    const float* gamma = (const float*)d_in[3];
    const float* beta  = (const float*)d_in[4];
    float* out = (float*)d_out;

    int rows = in_sizes[0] / NN;

    cudaFuncSetAttribute(fused_mma_kernel, cudaFuncAttributeMaxDynamicSharedMemorySize, SMEM_TOTAL);
    fused_mma_kernel<<<152, TPB, SMEM_TOTAL>>>(x, W1, W2, gamma, beta, out, rows);
}

// round 13
// speedup vs baseline: 1.4739x; 1.1758x over previous
#include <cuda_runtime.h>
#include <cuda_fp16.h>
#include <math.h>
#include <stdint.h>

#define NN   96
#define HH   192
#define TPB  384
#define RPT  (12 * 16)   // 12 warps x m16 rows
#define EPSV 1e-6f

// ---------------- smem layout (bytes) ----------------
#define OFF_G     0                       // float gamma[96]
#define OFF_B     384                     // float beta[96]
#define OFF_M     768                     // float m[96]  (column means of D)
#define OFF_B2    1152                    // float b[192] (W1 @ beta)
#define OFF_EHI   1920                    // E' = (W1*gamma)@D - a m^T : 192 x 96, f16
#define STR_E     208
#define SZ_E      (192 * 208)             // 39936
#define OFF_W2HI  (OFF_EHI + SZ_E)        // 41856 ; also fp32 D scratch during staging (36864 B)
#define STR_W2    400
#define SZ_W2     (96 * 400)              // 38400
#define SMEM_TOTAL (OFF_W2HI + SZ_W2)     // 80256

__device__ __forceinline__ uint32_t smem_u32(const void* p) {
    uint32_t a;
    asm("{ .reg .u64 t; cvta.to.shared.u64 t, %1; cvt.u32.u64 %0, t; }" : "=r"(a) : "l"(p));
    return a;
}

#define LDSM4(d0, d1, d2, d3, a) \
    asm volatile("ldmatrix.sync.aligned.m8n8.x4.shared.b16 {%0,%1,%2,%3}, [%4];" \
        : "=r"(d0), "=r"(d1), "=r"(d2), "=r"(d3) : "r"(a))

#define MMA(ac, A, b0, b1) \
    asm volatile("mma.sync.aligned.m16n8k16.row.col.f32.f16.f16.f32 " \
        "{%0,%1,%2,%3}, {%4,%5,%6,%7}, {%8,%9}, {%0,%1,%2,%3};" \
        : "+f"((ac)[0]), "+f"((ac)[1]), "+f"((ac)[2]), "+f"((ac)[3]) \
        : "r"((A)[0]), "r"((A)[1]), "r"((A)[2]), "r"((A)[3]), "r"(b0), "r"(b1))

__device__ __forceinline__ void sp2(float a, float b, uint32_t& hi, uint32_t& lo) {
    __half2 h = __floats2half2_rn(a, b);
    float ra = a - __low2float(h);
    float rb = b - __high2float(h);
    __half2 l = __floats2half2_rn(ra, rb);
    hi = *(uint32_t*)&h;
    lo = *(uint32_t*)&l;
}

__device__ __forceinline__ float fast_sigmoid(float v) {
    float t;
    asm("tanh.approx.f32 %0, %1;" : "=f"(t) : "f"(v * 0.5f));
    return fmaf(t, 0.5f, 0.5f);
}

extern __shared__ char sm[];

__global__ void __launch_bounds__(TPB, 1)
fused_mma_kernel(const float* __restrict__ x,
                 const float* __restrict__ W1,
                 const float* __restrict__ W2,
                 const float* __restrict__ gamma,
                 const float* __restrict__ beta,
                 float* __restrict__ out,
                 int rows) {
    const int tid  = threadIdx.x;
    const int lane = tid & 31;
    const int warp = tid >> 5;
    const int gid  = lane >> 2;
    const int tig  = lane & 3;
    const uint32_t sb = smem_u32(sm);

    float* sg  = (float*)(sm + OFF_G);
    float* sbt = (float*)(sm + OFF_B);
    float* smv = (float*)(sm + OFF_M);
    float* sb2 = (float*)(sm + OFF_B2);
    float* D32 = (float*)(sm + OFF_W2HI);   // staging scratch

    // ========== STAGE 1: gamma/beta + fp32 DCT matrix into scratch ==========
    if (tid < 96) { sg[tid] = gamma[tid]; sbt[tid] = beta[tid]; }
    const float PI192 = 0.016362461737446838f;
    for (int t = tid; t < 96 * 96; t += TPB) {
        int k = t / 96, i = t % 96;
        int mm = ((2 * i + 1) * k) % 384;
        D32[t] = 2.0f * cosf(PI192 * (float)mm);
    }
    __syncthreads();

    // ========== STAGE 2: m (col means of D), b = W1@beta ==========
    if (tid < 96) {
        float s = 0.f;
        for (int k = 0; k < 96; k++) s += D32[k * 96 + tid];
        smv[tid] = s * (1.0f / 96.0f);
    }
    if (tid < 192) {
        float bbv = 0.f;
        for (int k = 0; k < 96; k++) bbv = fmaf(W1[tid * 96 + k], sbt[k], bbv);
        sb2[tid] = bbv;
    }
    __syncthreads();

    // ========== STAGE 3: E' = (W1*gamma)@D - a m^T (f16 hi only) ==========
    {
        int bn = (tid >> 3) * 4;       // n-block 0..188
        int bi = (tid & 7) * 12;       // i-block 0..84
        float ea[4][12];
        float aa[4] = {0.f, 0.f, 0.f, 0.f};
#pragma unroll
        for (int n2 = 0; n2 < 4; n2++)
#pragma unroll
            for (int ii = 0; ii < 12; ii++) ea[n2][ii] = 0.f;
        for (int k = 0; k < 96; k++) {
            float gk = sg[k];
            float w0 = W1[(bn + 0) * 96 + k] * gk;
            float w1 = W1[(bn + 1) * 96 + k] * gk;
            float w2 = W1[(bn + 2) * 96 + k] * gk;
            float w3 = W1[(bn + 3) * 96 + k] * gk;
            aa[0] += w0; aa[1] += w1; aa[2] += w2; aa[3] += w3;
#pragma unroll
            for (int ii = 0; ii < 12; ii += 2) {
                float2 dv = *(float2*)(D32 + k * 96 + bi + ii);
                ea[0][ii] = fmaf(w0, dv.x, ea[0][ii]); ea[0][ii+1] = fmaf(w0, dv.y, ea[0][ii+1]);
                ea[1][ii] = fmaf(w1, dv.x, ea[1][ii]); ea[1][ii+1] = fmaf(w1, dv.y, ea[1][ii+1]);
                ea[2][ii] = fmaf(w2, dv.x, ea[2][ii]); ea[2][ii+1] = fmaf(w2, dv.y, ea[2][ii+1]);
                ea[3][ii] = fmaf(w3, dv.x, ea[3][ii]); ea[3][ii+1] = fmaf(w3, dv.y, ea[3][ii+1]);
            }
        }
        // stash E' rows in registers is not possible across syncthreads safely before
        // scratch reuse, so write hi to a temporary area: write AFTER sync below.
        // E' region (OFF_EHI) does not overlap D32 scratch (OFF_W2HI), so direct write is safe.
#pragma unroll
        for (int n2 = 0; n2 < 4; n2++)
#pragma unroll
            for (int ii = 0; ii < 12; ii++) {
                float v = ea[n2][ii] - aa[n2] * smv[bi + ii];   // fold -a m^T
                int off = (bn + n2) * STR_E + (bi + ii) * 2;
                *(__half*)(sm + OFF_EHI + off) = __float2half_rn(v);
            }
    }
    __syncthreads();

    // ========== STAGE 4: W2 f16 hi (overwrites D scratch) ==========
    for (int t = tid; t < 96 * 192; t += TPB) {
        int n = t / 192, i = t % 192;
        *(__half*)(sm + OFF_W2HI + n * STR_W2 + i * 2) = __float2half_rn(W2[t]);
    }
    __syncthreads();

    const uint32_t lrow = lane & 7;
    const uint32_t lkb  = (uint32_t)(lane >> 3) * 16;
    const uint32_t bEh  = sb + OFF_EHI  + lrow * STR_E  + lkb;
    const uint32_t bW2h = sb + OFF_W2HI + lrow * STR_W2 + lkb;

    const int ntiles = (rows + RPT - 1) / RPT;

    for (int tile = blockIdx.x; tile < ntiles; tile += gridDim.x) {
        const int r0 = tile * RPT + warp * 16 + gid;
        const int r1 = r0 + 8;
        const float* xr0 = x + (size_t)min(r0, rows - 1) * NN;
        const float* xr1 = x + (size_t)min(r1, rows - 1) * NN;

        // ===== load x, build split A-fragments, accumulate LN1 stats from x =====
        uint32_t a2h[6][4], a2l[6][4];
        float s1_0 = 0.f, sq_0 = 0.f, sm_0 = 0.f;
        float s1_1 = 0.f, sq_1 = 0.f, sm_1 = 0.f;
#pragma unroll
        for (int ktp = 0; ktp < 3; ktp++) {
            int kb = 32 * ktp + 2 * tig;
#pragma unroll
            for (int p = 0; p < 4; p++) {
                float2 v0 = *(const float2*)(xr0 + kb + 8 * p);
                float2 v1 = *(const float2*)(xr1 + kb + 8 * p);
                float2 mv = *(const float2*)(smv + kb + 8 * p);
                s1_0 += v0.x + v0.y;
                sq_0 = fmaf(v0.x, v0.x, fmaf(v0.y, v0.y, sq_0));
                sm_0 = fmaf(v0.x, mv.x, fmaf(v0.y, mv.y, sm_0));
                s1_1 += v1.x + v1.y;
                sq_1 = fmaf(v1.x, v1.x, fmaf(v1.y, v1.y, sq_1));
                sm_1 = fmaf(v1.x, mv.x, fmaf(v1.y, mv.y, sm_1));
                int kk = 2 * ktp + (p >> 1);
                int of = (p & 1) * 2;
                sp2(v0.x, v0.y, a2h[kk][of],     a2l[kk][of]);
                sp2(v1.x, v1.y, a2h[kk][of + 1], a2l[kk][of + 1]);
            }
        }
        s1_0 += __shfl_xor_sync(~0u, s1_0, 1); s1_0 += __shfl_xor_sync(~0u, s1_0, 2);
        sq_0 += __shfl_xor_sync(~0u, sq_0, 1); sq_0 += __shfl_xor_sync(~0u, sq_0, 2);
        sm_0 += __shfl_xor_sync(~0u, sm_0, 1); sm_0 += __shfl_xor_sync(~0u, sm_0, 2);
        s1_1 += __shfl_xor_sync(~0u, s1_1, 1); s1_1 += __shfl_xor_sync(~0u, s1_1, 2);
        sq_1 += __shfl_xor_sync(~0u, sq_1, 1); sq_1 += __shfl_xor_sync(~0u, sq_1, 2);
        sm_1 += __shfl_xor_sync(~0u, sm_1, 1); sm_1 += __shfl_xor_sync(~0u, sm_1, 2);
        // LN1 via DCT row structure: sum(y^2) = 192*||x||^2 + 2*(sum x)^2 ; mu = x.m
        float var0 = 2.0f * sq_0 + s1_0 * s1_0 * (1.0f / 48.0f) - sm_0 * sm_0;
        float var1 = 2.0f * sq_1 + s1_1 * s1_1 * (1.0f / 48.0f) - sm_1 * sm_1;
        float rs0 = rsqrtf(var0 + EPSV);
        float rs1 = rsqrtf(var1 + EPSV);

        // ========== Fused GEMM-E' (x@E'^T -> rs*z+b -> relu) -> GEMM3 ==========
        float sfr[12][4];
#pragma unroll
        for (int i = 0; i < 12; i++) { sfr[i][0] = sfr[i][1] = sfr[i][2] = sfr[i][3] = 0.f; }

#pragma unroll
        for (int g = 0; g < 6; g++) {
            float ac2[4][4];
#pragma unroll
            for (int j = 0; j < 4; j++) { ac2[j][0] = ac2[j][1] = ac2[j][2] = ac2[j][3] = 0.f; }
#pragma unroll
            for (int ktp = 0; ktp < 3; ktp++) {
                uint32_t wh[4][4];
#pragma unroll
                for (int j = 0; j < 4; j++) {
                    int nt = 4 * g + j;
                    LDSM4(wh[j][0], wh[j][1], wh[j][2], wh[j][3], bEh + nt * (8 * STR_E) + ktp * 64);
                }
#pragma unroll
                for (int j = 0; j < 4; j++) MMA(ac2[j], a2h[2*ktp],     wh[j][0], wh[j][1]);
#pragma unroll
                for (int j = 0; j < 4; j++) MMA(ac2[j], a2l[2*ktp],     wh[j][0], wh[j][1]);
#pragma unroll
                for (int j = 0; j < 4; j++) MMA(ac2[j], a2h[2*ktp + 1], wh[j][2], wh[j][3]);
#pragma unroll
                for (int j = 0; j < 4; j++) MMA(ac2[j], a2l[2*ktp + 1], wh[j][2], wh[j][3]);
            }
            // rs*z + b, relu, pack -> GEMM3 k32 A-fragments
            uint32_t h0h[4], h0l[4], h1h[4], h1l[4];
#pragma unroll
            for (int j = 0; j < 4; j++) {
                int nt = 4 * g + j;
                float2 bv = *(const float2*)(sb2 + 8 * nt + 2 * tig);
                float e0 = fmaxf(fmaf(rs0, ac2[j][0], bv.x), 0.f);
                float e1 = fmaxf(fmaf(rs0, ac2[j][1], bv.y), 0.f);
                float e2 = fmaxf(fmaf(rs1, ac2[j][2], bv.x), 0.f);
                float e3 = fmaxf(fmaf(rs1, ac2[j][3], bv.y), 0.f);
                if (j < 2) {
                    sp2(e0, e1, h0h[2 * j],     h0l[2 * j]);
                    sp2(e2, e3, h0h[2 * j + 1], h0l[2 * j + 1]);
                } else {
                    sp2(e0, e1, h1h[2 * (j - 2)],     h1l[2 * (j - 2)]);
                    sp2(e2, e3, h1h[2 * (j - 2) + 1], h1l[2 * (j - 2) + 1]);
                }
            }

            // GEMM3 k32 update: W2 hi-only, h-residual kept
#pragma unroll
            for (int jb = 0; jb < 3; jb++) {
                uint32_t vh[4][4];
#pragma unroll
                for (int j = 0; j < 4; j++) {
                    int nt = 4 * jb + j;
                    LDSM4(vh[j][0], vh[j][1], vh[j][2], vh[j][3], bW2h + nt * (8 * STR_W2) + g * 64);
                }
#pragma unroll
                for (int j = 0; j < 4; j++) MMA(sfr[4*jb+j], h0h, vh[j][0], vh[j][1]);
#pragma unroll
                for (int j = 0; j < 4; j++) MMA(sfr[4*jb+j], h0l, vh[j][0], vh[j][1]);
#pragma unroll
                for (int j = 0; j < 4; j++) MMA(sfr[4*jb+j], h1h, vh[j][2], vh[j][3]);
#pragma unroll
                for (int j = 0; j < 4; j++) MMA(sfr[4*jb+j], h1l, vh[j][2], vh[j][3]);
            }
        }

        // ================= sigmoid + LayerNorm 2 + output =================
#pragma unroll
        for (int nt = 0; nt < 12; nt++)
#pragma unroll
            for (int q = 0; q < 4; q++)
                sfr[nt][q] = fast_sigmoid(sfr[nt][q]);

        float t0 = 0.f, t1 = 0.f;
#pragma unroll
        for (int nt = 0; nt < 12; nt++) { t0 += sfr[nt][0] + sfr[nt][1]; t1 += sfr[nt][2] + sfr[nt][3]; }
        t0 += __shfl_xor_sync(~0u, t0, 1); t0 += __shfl_xor_sync(~0u, t0, 2);
        t1 += __shfl_xor_sync(~0u, t1, 1); t1 += __shfl_xor_sync(~0u, t1, 2);
        float m20 = t0 * (1.f/96.f), m21 = t1 * (1.f/96.f);
        float p0 = 0.f, p1 = 0.f;
#pragma unroll
        for (int nt = 0; nt < 12; nt++) {
            float d;
            d = sfr[nt][0] - m20; p0 = fmaf(d, d, p0);
            d = sfr[nt][1] - m20; p0 = fmaf(d, d, p0);
            d = sfr[nt][2] - m21; p1 = fmaf(d, d, p1);
            d = sfr[nt][3] - m21; p1 = fmaf(d, d, p1);
        }
        p0 += __shfl_xor_sync(~0u, p0, 1); p0 += __shfl_xor_sync(~0u, p0, 2);
        p1 += __shfl_xor_sync(~0u, p1, 1); p1 += __shfl_xor_sync(~0u, p1, 2);
        float rz0 = rsqrtf(p0 * (1.f/96.f) + EPSV);
        float rz1 = rsqrtf(p1 * (1.f/96.f) + EPSV);

#pragma unroll
        for (int nt = 0; nt < 12; nt++) {
            int col = 8 * nt + 2 * tig;
            float2 gv = *(const float2*)(sg  + col);
            float2 bv = *(const float2*)(sbt + col);
            float w00 = fmaf((sfr[nt][0] - m20) * rz0, gv.x, bv.x);
            float w01 = fmaf((sfr[nt][1] - m20) * rz0, gv.y, bv.y);
            float w10 = fmaf((sfr[nt][2] - m21) * rz1, gv.x, bv.x);
            float w11 = fmaf((sfr[nt][3] - m21) * rz1, gv.y, bv.y);
            if (r0 < rows) {
                float2 xv = *(const float2*)(x + (size_t)r0 * NN + col);
                float2 o; o.x = xv.x * w00; o.y = xv.y * w01;
                *(float2*)(out + (size_t)r0 * NN + col) = o;
            }
            if (r1 < rows) {
                float2 xv = *(const float2*)(x + (size_t)r1 * NN + col);
                float2 o; o.x = xv.x * w10; o.y = xv.y * w11;
                *(float2*)(out + (size_t)r1 * NN + col) = o;
            }
        }
    }
}

extern "C" void kernel_launch(void* const* d_in, const int* in_sizes, int n_in,
                              void* d_out, int out_size) {
    const float* x     = (const float*)d_in[0];
    const float* W1    = (const float*)d_in[1];
    const float* W2    = (const float*)d_in[2];
    const float* gamma = (const float*)d_in[3];
    const float* beta  = (const float*)d_in[4];
    float* out = (float*)d_out;

    int rows = in_sizes[0] / NN;

    cudaFuncSetAttribute(fused_mma_kernel, cudaFuncAttributeMaxDynamicSharedMemorySize, SMEM_TOTAL);
    fused_mma_kernel<<<152, TPB, SMEM_TOTAL>>>(x, W1, W2, gamma, beta, out, rows);
}

// round 14
// speedup vs baseline: 1.8467x; 1.2529x over previous
#include <cuda_runtime.h>
#include <cuda_fp16.h>
#include <math.h>
#include <stdint.h>

#define NN   96
#define HH   192
#define TPB  256
#define RPT  (8 * 32)    // 8 warps x 32 rows
#define EPSV 1e-6f

// ---------------- smem layout (bytes) ----------------
#define OFF_G     0                       // float gamma[96]
#define OFF_B     384                     // float beta[96]
#define OFF_M     768                     // float m[96]  (column means of D)
#define OFF_B2    1152                    // float b[192] (W1 @ beta)
#define OFF_EHI   1920                    // E' = (W1*gamma)@D - a m^T : 192 x 96, f16
#define STR_E     208
#define SZ_E      (192 * 208)             // 39936
#define OFF_W2HI  (OFF_EHI + SZ_E)        // 41856 ; also fp32 D scratch during staging
#define STR_W2    400
#define SZ_W2     (96 * 400)              // 38400
#define SMEM_TOTAL (OFF_W2HI + SZ_W2)     // 80256

__device__ __forceinline__ uint32_t smem_u32(const void* p) {
    uint32_t a;
    asm("{ .reg .u64 t; cvta.to.shared.u64 t, %1; cvt.u32.u64 %0, t; }" : "=r"(a) : "l"(p));
    return a;
}

#define LDSM4(d0, d1, d2, d3, a) \
    asm volatile("ldmatrix.sync.aligned.m8n8.x4.shared.b16 {%0,%1,%2,%3}, [%4];" \
        : "=r"(d0), "=r"(d1), "=r"(d2), "=r"(d3) : "r"(a))

#define MMA(ac, A, b0, b1) \
    asm volatile("mma.sync.aligned.m16n8k16.row.col.f32.f16.f16.f32 " \
        "{%0,%1,%2,%3}, {%4,%5,%6,%7}, {%8,%9}, {%0,%1,%2,%3};" \
        : "+f"((ac)[0]), "+f"((ac)[1]), "+f"((ac)[2]), "+f"((ac)[3]) \
        : "r"((A)[0]), "r"((A)[1]), "r"((A)[2]), "r"((A)[3]), "r"(b0), "r"(b1))

__device__ __forceinline__ uint32_t pk2(float a, float b) {
    __half2 h = __floats2half2_rn(a, b);
    return *(uint32_t*)&h;
}

__device__ __forceinline__ float fast_sigmoid(float v) {
    float t;
    asm("tanh.approx.f32 %0, %1;" : "=f"(t) : "f"(v * 0.5f));
    return fmaf(t, 0.5f, 0.5f);
}

extern __shared__ char sm[];

__global__ void __launch_bounds__(TPB, 1)
fused_mma_kernel(const float* __restrict__ x,
                 const float* __restrict__ W1,
                 const float* __restrict__ W2,
                 const float* __restrict__ gamma,
                 const float* __restrict__ beta,
                 float* __restrict__ out,
                 int rows) {
    const int tid  = threadIdx.x;
    const int lane = tid & 31;
    const int warp = tid >> 5;
    const int gid  = lane >> 2;
    const int tig  = lane & 3;
    const uint32_t sb = smem_u32(sm);

    float* sg  = (float*)(sm + OFF_G);
    float* sbt = (float*)(sm + OFF_B);
    float* smv = (float*)(sm + OFF_M);
    float* sb2 = (float*)(sm + OFF_B2);
    float* D32 = (float*)(sm + OFF_W2HI);   // staging scratch

    // ========== STAGE 1: gamma/beta + fp32 DCT matrix into scratch ==========
    if (tid < 96) { sg[tid] = gamma[tid]; sbt[tid] = beta[tid]; }
    const float PI192 = 0.016362461737446838f;
    for (int t = tid; t < 96 * 96; t += TPB) {
        int k = t / 96, i = t % 96;
        int mm = ((2 * i + 1) * k) % 384;
        D32[t] = 2.0f * cosf(PI192 * (float)mm);
    }
    __syncthreads();

    // ========== STAGE 2: m (col means of D), b = W1@beta ==========
    if (tid < 96) {
        float s = 0.f;
        for (int k = 0; k < 96; k++) s += D32[k * 96 + tid];
        smv[tid] = s * (1.0f / 96.0f);
    }
    if (tid < 192) {
        float bbv = 0.f;
        for (int k = 0; k < 96; k++) bbv = fmaf(W1[tid * 96 + k], sbt[k], bbv);
        sb2[tid] = bbv;
    }
    __syncthreads();

    // ========== STAGE 3: E' = (W1*gamma)@D - a m^T (f16 hi only) ==========
    // 256 threads: each does 6 E-rows x 12 cols
    {
        int bn = (tid >> 3) * 6;       // n-block 0..186
        int bi = (tid & 7) * 12;       // i-block 0..84
        float ea[6][12];
        float aa[6] = {0.f, 0.f, 0.f, 0.f, 0.f, 0.f};
#pragma unroll
        for (int n2 = 0; n2 < 6; n2++)
#pragma unroll
            for (int ii = 0; ii < 12; ii++) ea[n2][ii] = 0.f;
        for (int k = 0; k < 96; k++) {
            float gk = sg[k];
            float wv[6];
#pragma unroll
            for (int n2 = 0; n2 < 6; n2++) {
                wv[n2] = W1[(bn + n2) * 96 + k] * gk;
                aa[n2] += wv[n2];
            }
#pragma unroll
            for (int ii = 0; ii < 12; ii += 2) {
                float2 dv = *(float2*)(D32 + k * 96 + bi + ii);
#pragma unroll
                for (int n2 = 0; n2 < 6; n2++) {
                    ea[n2][ii]     = fmaf(wv[n2], dv.x, ea[n2][ii]);
                    ea[n2][ii + 1] = fmaf(wv[n2], dv.y, ea[n2][ii + 1]);
                }
            }
        }
#pragma unroll
        for (int n2 = 0; n2 < 6; n2++)
#pragma unroll
            for (int ii = 0; ii < 12; ii++) {
                float v = ea[n2][ii] - aa[n2] * smv[bi + ii];   // fold -a m^T
                int off = (bn + n2) * STR_E + (bi + ii) * 2;
                *(__half*)(sm + OFF_EHI + off) = __float2half_rn(v);
            }
    }
    __syncthreads();

    // ========== STAGE 4: W2 f16 hi (overwrites D scratch) ==========
    for (int t = tid; t < 96 * 192; t += TPB) {
        int n = t / 192, i = t % 192;
        *(__half*)(sm + OFF_W2HI + n * STR_W2 + i * 2) = __float2half_rn(W2[t]);
    }
    __syncthreads();

    const uint32_t lrow = lane & 7;
    const uint32_t lkb  = (uint32_t)(lane >> 3) * 16;
    const uint32_t bEh  = sb + OFF_EHI  + lrow * STR_E  + lkb;
    const uint32_t bW2h = sb + OFF_W2HI + lrow * STR_W2 + lkb;

    const int ntiles = (rows + RPT - 1) / RPT;

    for (int tile = blockIdx.x; tile < ntiles; tile += gridDim.x) {
        const int r0 = tile * RPT + warp * 32 + gid;   // group A: r0, r0+8; group B: r0+16, r0+24
        const float* xr0 = x + (size_t)min(r0,      rows - 1) * NN;
        const float* xr1 = x + (size_t)min(r0 + 8,  rows - 1) * NN;
        const float* xr2 = x + (size_t)min(r0 + 16, rows - 1) * NN;
        const float* xr3 = x + (size_t)min(r0 + 24, rows - 1) * NN;

        // ===== load x (4 rows), build f16 A-fragments, accumulate LN1 stats =====
        uint32_t a2h[6][8];
        float s1_0 = 0.f, sq_0 = 0.f, sm_0 = 0.f;
        float s1_1 = 0.f, sq_1 = 0.f, sm_1 = 0.f;
        float s1_2 = 0.f, sq_2 = 0.f, sm_2 = 0.f;
        float s1_3 = 0.f, sq_3 = 0.f, sm_3 = 0.f;
#pragma unroll
        for (int ktp = 0; ktp < 3; ktp++) {
            int kb = 32 * ktp + 2 * tig;
#pragma unroll
            for (int p = 0; p < 4; p++) {
                float2 v0 = *(const float2*)(xr0 + kb + 8 * p);
                float2 v1 = *(const float2*)(xr1 + kb + 8 * p);
                float2 v2 = *(const float2*)(xr2 + kb + 8 * p);
                float2 v3 = *(const float2*)(xr3 + kb + 8 * p);
                float2 mv = *(const float2*)(smv + kb + 8 * p);
                s1_0 += v0.x + v0.y;
                sq_0 = fmaf(v0.x, v0.x, fmaf(v0.y, v0.y, sq_0));
                sm_0 = fmaf(v0.x, mv.x, fmaf(v0.y, mv.y, sm_0));
                s1_1 += v1.x + v1.y;
                sq_1 = fmaf(v1.x, v1.x, fmaf(v1.y, v1.y, sq_1));
                sm_1 = fmaf(v1.x, mv.x, fmaf(v1.y, mv.y, sm_1));
                s1_2 += v2.x + v2.y;
                sq_2 = fmaf(v2.x, v2.x, fmaf(v2.y, v2.y, sq_2));
                sm_2 = fmaf(v2.x, mv.x, fmaf(v2.y, mv.y, sm_2));
                s1_3 += v3.x + v3.y;
                sq_3 = fmaf(v3.x, v3.x, fmaf(v3.y, v3.y, sq_3));
                sm_3 = fmaf(v3.x, mv.x, fmaf(v3.y, mv.y, sm_3));
                int kk = 2 * ktp + (p >> 1);
                int of = (p & 1) * 2;
                a2h[kk][of]     = pk2(v0.x, v0.y);
                a2h[kk][of + 1] = pk2(v1.x, v1.y);
                a2h[kk][of + 4] = pk2(v2.x, v2.y);
                a2h[kk][of + 5] = pk2(v3.x, v3.y);
            }
        }
        s1_0 += __shfl_xor_sync(~0u, s1_0, 1); s1_0 += __shfl_xor_sync(~0u, s1_0, 2);
        sq_0 += __shfl_xor_sync(~0u, sq_0, 1); sq_0 += __shfl_xor_sync(~0u, sq_0, 2);
        sm_0 += __shfl_xor_sync(~0u, sm_0, 1); sm_0 += __shfl_xor_sync(~0u, sm_0, 2);
        s1_1 += __shfl_xor_sync(~0u, s1_1, 1); s1_1 += __shfl_xor_sync(~0u, s1_1, 2);
        sq_1 += __shfl_xor_sync(~0u, sq_1, 1); sq_1 += __shfl_xor_sync(~0u, sq_1, 2);
        sm_1 += __shfl_xor_sync(~0u, sm_1, 1); sm_1 += __shfl_xor_sync(~0u, sm_1, 2);
        s1_2 += __shfl_xor_sync(~0u, s1_2, 1); s1_2 += __shfl_xor_sync(~0u, s1_2, 2);
        sq_2 += __shfl_xor_sync(~0u, sq_2, 1); sq_2 += __shfl_xor_sync(~0u, sq_2, 2);
        sm_2 += __shfl_xor_sync(~0u, sm_2, 1); sm_2 += __shfl_xor_sync(~0u, sm_2, 2);
        s1_3 += __shfl_xor_sync(~0u, s1_3, 1); s1_3 += __shfl_xor_sync(~0u, s1_3, 2);
        sq_3 += __shfl_xor_sync(~0u, sq_3, 1); sq_3 += __shfl_xor_sync(~0u, sq_3, 2);
        sm_3 += __shfl_xor_sync(~0u, sm_3, 1); sm_3 += __shfl_xor_sync(~0u, sm_3, 2);
        // LN1 via DCT structure: var = 2*||x||^2 + (sum x)^2/48 - mu^2 ; mu = x.m
        float rs0 = rsqrtf(2.0f * sq_0 + s1_0 * s1_0 * (1.0f / 48.0f) - sm_0 * sm_0 + EPSV);
        float rs1 = rsqrtf(2.0f * sq_1 + s1_1 * s1_1 * (1.0f / 48.0f) - sm_1 * sm_1 + EPSV);
        float rs2 = rsqrtf(2.0f * sq_2 + s1_2 * s1_2 * (1.0f / 48.0f) - sm_2 * sm_2 + EPSV);
        float rs3 = rsqrtf(2.0f * sq_3 + s1_3 * s1_3 * (1.0f / 48.0f) - sm_3 * sm_3 + EPSV);

        // ========== Fused GEMM-E' -> (rs*z+b, relu) -> GEMM3, M=32 ==========
        float sfr[12][8];
#pragma unroll
        for (int i = 0; i < 12; i++)
#pragma unroll
            for (int q = 0; q < 8; q++) sfr[i][q] = 0.f;

#pragma unroll
        for (int g = 0; g < 6; g++) {
            float ac2[4][8];
#pragma unroll
            for (int j = 0; j < 4; j++)
#pragma unroll
                for (int q = 0; q < 8; q++) ac2[j][q] = 0.f;
#pragma unroll
            for (int ktp = 0; ktp < 3; ktp++) {
                uint32_t wh[4][4];
#pragma unroll
                for (int j = 0; j < 4; j++) {
                    int nt = 4 * g + j;
                    LDSM4(wh[j][0], wh[j][1], wh[j][2], wh[j][3], bEh + nt * (8 * STR_E) + ktp * 64);
                }
#pragma unroll
                for (int j = 0; j < 4; j++) MMA(ac2[j],     a2h[2*ktp],         wh[j][0], wh[j][1]);
#pragma unroll
                for (int j = 0; j < 4; j++) MMA(ac2[j] + 4, a2h[2*ktp] + 4,     wh[j][0], wh[j][1]);
#pragma unroll
                for (int j = 0; j < 4; j++) MMA(ac2[j],     a2h[2*ktp + 1],     wh[j][2], wh[j][3]);
#pragma unroll
                for (int j = 0; j < 4; j++) MMA(ac2[j] + 4, a2h[2*ktp + 1] + 4, wh[j][2], wh[j][3]);
            }
            // rs*z + b, relu, pack -> GEMM3 k32 A-fragments per row group
            uint32_t hA0[4], hA1[4], hB0[4], hB1[4];
#pragma unroll
            for (int j = 0; j < 4; j++) {
                int nt = 4 * g + j;
                float2 bv = *(const float2*)(sb2 + 8 * nt + 2 * tig);
                float eA0 = fmaxf(fmaf(rs0, ac2[j][0], bv.x), 0.f);
                float eA1 = fmaxf(fmaf(rs0, ac2[j][1], bv.y), 0.f);
                float eA2 = fmaxf(fmaf(rs1, ac2[j][2], bv.x), 0.f);
                float eA3 = fmaxf(fmaf(rs1, ac2[j][3], bv.y), 0.f);
                float eB0 = fmaxf(fmaf(rs2, ac2[j][4], bv.x), 0.f);
                float eB1 = fmaxf(fmaf(rs2, ac2[j][5], bv.y), 0.f);
                float eB2 = fmaxf(fmaf(rs3, ac2[j][6], bv.x), 0.f);
                float eB3 = fmaxf(fmaf(rs3, ac2[j][7], bv.y), 0.f);
                if (j < 2) {
                    hA0[2 * j]     = pk2(eA0, eA1);
                    hA0[2 * j + 1] = pk2(eA2, eA3);
                    hB0[2 * j]     = pk2(eB0, eB1);
                    hB0[2 * j + 1] = pk2(eB2, eB3);
                } else {
                    hA1[2 * (j - 2)]     = pk2(eA0, eA1);
                    hA1[2 * (j - 2) + 1] = pk2(eA2, eA3);
                    hB1[2 * (j - 2)]     = pk2(eB0, eB1);
                    hB1[2 * (j - 2) + 1] = pk2(eB2, eB3);
                }
            }

            // GEMM3 k32 update, both row groups reuse each weight fragment
#pragma unroll
            for (int jb = 0; jb < 3; jb++) {
                uint32_t vh[4][4];
#pragma unroll
                for (int j = 0; j < 4; j++) {
                    int nt = 4 * jb + j;
                    LDSM4(vh[j][0], vh[j][1], vh[j][2], vh[j][3], bW2h + nt * (8 * STR_W2) + g * 64);
                }
#pragma unroll
                for (int j = 0; j < 4; j++) MMA(sfr[4*jb+j],     hA0, vh[j][0], vh[j][1]);
#pragma unroll
                for (int j = 0; j < 4; j++) MMA(sfr[4*jb+j] + 4, hB0, vh[j][0], vh[j][1]);
#pragma unroll
                for (int j = 0; j < 4; j++) MMA(sfr[4*jb+j],     hA1, vh[j][2], vh[j][3]);
#pragma unroll
                for (int j = 0; j < 4; j++) MMA(sfr[4*jb+j] + 4, hB1, vh[j][2], vh[j][3]);
            }
        }

        // ================= sigmoid + LayerNorm 2 + output (4 rows) =================
#pragma unroll
        for (int nt = 0; nt < 12; nt++)
#pragma unroll
            for (int q = 0; q < 8; q++)
                sfr[nt][q] = fast_sigmoid(sfr[nt][q]);

        float t0 = 0.f, t1 = 0.f, t2 = 0.f, t3 = 0.f;
#pragma unroll
        for (int nt = 0; nt < 12; nt++) {
            t0 += sfr[nt][0] + sfr[nt][1]; t1 += sfr[nt][2] + sfr[nt][3];
            t2 += sfr[nt][4] + sfr[nt][5]; t3 += sfr[nt][6] + sfr[nt][7];
        }
        t0 += __shfl_xor_sync(~0u, t0, 1); t0 += __shfl_xor_sync(~0u, t0, 2);
        t1 += __shfl_xor_sync(~0u, t1, 1); t1 += __shfl_xor_sync(~0u, t1, 2);
        t2 += __shfl_xor_sync(~0u, t2, 1); t2 += __shfl_xor_sync(~0u, t2, 2);
        t3 += __shfl_xor_sync(~0u, t3, 1); t3 += __shfl_xor_sync(~0u, t3, 2);
        float m0 = t0 * (1.f/96.f), m1 = t1 * (1.f/96.f), m2 = t2 * (1.f/96.f), m3 = t3 * (1.f/96.f);
        float p0 = 0.f, p1 = 0.f, p2 = 0.f, p3 = 0.f;
#pragma unroll
        for (int nt = 0; nt < 12; nt++) {
            float d;
            d = sfr[nt][0] - m0; p0 = fmaf(d, d, p0);
            d = sfr[nt][1] - m0; p0 = fmaf(d, d, p0);
            d = sfr[nt][2] - m1; p1 = fmaf(d, d, p1);
            d = sfr[nt][3] - m1; p1 = fmaf(d, d, p1);
            d = sfr[nt][4] - m2; p2 = fmaf(d, d, p2);
            d = sfr[nt][5] - m2; p2 = fmaf(d, d, p2);
            d = sfr[nt][6] - m3; p3 = fmaf(d, d, p3);
            d = sfr[nt][7] - m3; p3 = fmaf(d, d, p3);
        }
        p0 += __shfl_xor_sync(~0u, p0, 1); p0 += __shfl_xor_sync(~0u, p0, 2);
        p1 += __shfl_xor_sync(~0u, p1, 1); p1 += __shfl_xor_sync(~0u, p1, 2);
        p2 += __shfl_xor_sync(~0u, p2, 1); p2 += __shfl_xor_sync(~0u, p2, 2);
        p3 += __shfl_xor_sync(~0u, p3, 1); p3 += __shfl_xor_sync(~0u, p3, 2);
        float z0 = rsqrtf(p0 * (1.f/96.f) + EPSV);
        float z1 = rsqrtf(p1 * (1.f/96.f) + EPSV);
        float z2 = rsqrtf(p2 * (1.f/96.f) + EPSV);
        float z3 = rsqrtf(p3 * (1.f/96.f) + EPSV);

#pragma unroll
        for (int nt = 0; nt < 12; nt++) {
            int col = 8 * nt + 2 * tig;
            float2 gv = *(const float2*)(sg  + col);
            float2 bv = *(const float2*)(sbt + col);
            int rr[4] = { r0, r0 + 8, r0 + 16, r0 + 24 };
            float mm[4] = { m0, m1, m2, m3 };
            float zz[4] = { z0, z1, z2, z3 };
#pragma unroll
            for (int gq = 0; gq < 4; gq++) {
                if (rr[gq] < rows) {
                    float wa = fmaf((sfr[nt][2 * gq]     - mm[gq]) * zz[gq], gv.x, bv.x);
                    float wb = fmaf((sfr[nt][2 * gq + 1] - mm[gq]) * zz[gq], gv.y, bv.y);
                    float2 xv = *(const float2*)(x + (size_t)rr[gq] * NN + col);
                    float2 o; o.x = xv.x * wa; o.y = xv.y * wb;
                    *(float2*)(out + (size_t)rr[gq] * NN + col) = o;
                }
            }
        }
    }
}

extern "C" void kernel_launch(void* const* d_in, const int* in_sizes, int n_in,
                              void* d_out, int out_size) {
    const float* x     = (const float*)d_in[0];
    const float* W1    = (const float*)d_in[1];
    const float* W2    = (const float*)d_in[2];
    const float* gamma = (const float*)d_in[3];
    const float* beta  = (const float*)d_in[4];
    float* out = (float*)d_out;

    int rows = in_sizes[0] / NN;

    cudaFuncSetAttribute(fused_mma_kernel, cudaFuncAttributeMaxDynamicSharedMemorySize, SMEM_TOTAL);
    fused_mma_kernel<<<152, TPB, SMEM_TOTAL>>>(x, W1, W2, gamma, beta, out, rows);
}

// round 15
// speedup vs baseline: 1.9656x; 1.0644x over previous
#include <cuda_runtime.h>
#include <cuda_fp16.h>
#include <math.h>
#include <stdint.h>

#define NN   96
#define HH   192
#define TPB  256
#define RPT  (8 * 32)    // 8 warps x 32 rows
#define EPSV 1e-6f

// ---------------- smem layout (bytes) ----------------
#define OFF_G     0                       // float gamma[96]
#define OFF_B     384                     // float beta[96]
#define OFF_M     768                     // float m[96]  (column means of D)
#define OFF_B2    1152                    // float b[192] (W1 @ beta)
#define OFF_EHI   1920                    // E' = (W1*gamma)@D - a m^T : 192 x 96, f16
#define STR_E     208
#define SZ_E      (192 * 208)             // 39936
#define OFF_W2HI  (OFF_EHI + SZ_E)        // 41856 ; also fp32 D scratch during staging
#define STR_W2    400
#define SZ_W2     (96 * 400)              // 38400
#define SMEM_TOTAL (OFF_W2HI + SZ_W2)     // 80256

__device__ __forceinline__ uint32_t smem_u32(const void* p) {
    uint32_t a;
    asm("{ .reg .u64 t; cvta.to.shared.u64 t, %1; cvt.u32.u64 %0, t; }" : "=r"(a) : "l"(p));
    return a;
}

#define LDSM4(d0, d1, d2, d3, a) \
    asm volatile("ldmatrix.sync.aligned.m8n8.x4.shared.b16 {%0,%1,%2,%3}, [%4];" \
        : "=r"(d0), "=r"(d1), "=r"(d2), "=r"(d3) : "r"(a))

#define MMA(ac, A, b0, b1) \
    asm volatile("mma.sync.aligned.m16n8k16.row.col.f32.f16.f16.f32 " \
        "{%0,%1,%2,%3}, {%4,%5,%6,%7}, {%8,%9}, {%0,%1,%2,%3};" \
        : "+f"((ac)[0]), "+f"((ac)[1]), "+f"((ac)[2]), "+f"((ac)[3]) \
        : "r"((A)[0]), "r"((A)[1]), "r"((A)[2]), "r"((A)[3]), "r"(b0), "r"(b1))

__device__ __forceinline__ uint32_t pk2(float a, float b) {
    __half2 h = __floats2half2_rn(a, b);
    return *(uint32_t*)&h;
}

__device__ __forceinline__ float fast_sigmoid(float v) {
    float t;
    asm("tanh.approx.f32 %0, %1;" : "=f"(t) : "f"(v * 0.5f));
    return fmaf(t, 0.5f, 0.5f);
}

extern __shared__ char sm[];

__global__ void __launch_bounds__(TPB, 1)
fused_mma_kernel(const float* __restrict__ x,
                 const float* __restrict__ W1,
                 const float* __restrict__ W2,
                 const float* __restrict__ gamma,
                 const float* __restrict__ beta,
                 float* __restrict__ out,
                 int rows) {
    const int tid  = threadIdx.x;
    const int lane = tid & 31;
    const int warp = tid >> 5;
    const int gid  = lane >> 2;
    const int tig  = lane & 3;
    const uint32_t sb = smem_u32(sm);

    float* sg  = (float*)(sm + OFF_G);
    float* sbt = (float*)(sm + OFF_B);
    float* smv = (float*)(sm + OFF_M);
    float* sb2 = (float*)(sm + OFF_B2);
    float* D32 = (float*)(sm + OFF_W2HI);   // staging scratch

    // ========== STAGE 1: gamma/beta + fp32 DCT matrix into scratch ==========
    if (tid < 96) { sg[tid] = gamma[tid]; sbt[tid] = beta[tid]; }
    const float PI192 = 0.016362461737446838f;
    for (int t = tid; t < 96 * 96; t += TPB) {
        int k = t / 96, i = t % 96;
        int mm = ((2 * i + 1) * k) % 384;
        D32[t] = 2.0f * cosf(PI192 * (float)mm);
    }
    __syncthreads();

    // ========== STAGE 2: m (col means of D), b = W1@beta ==========
    if (tid < 96) {
        float s = 0.f;
        for (int k = 0; k < 96; k++) s += D32[k * 96 + tid];
        smv[tid] = s * (1.0f / 96.0f);
    }
    if (tid < 192) {
        float bbv = 0.f;
        for (int k = 0; k < 96; k++) bbv = fmaf(W1[tid * 96 + k], sbt[k], bbv);
        sb2[tid] = bbv;
    }
    __syncthreads();

    // ========== STAGE 3: E' = (W1*gamma)@D - a m^T (f16 hi only) ==========
    {
        int bn = (tid >> 3) * 6;       // n-block 0..186
        int bi = (tid & 7) * 12;       // i-block 0..84
        float ea[6][12];
        float aa[6] = {0.f, 0.f, 0.f, 0.f, 0.f, 0.f};
#pragma unroll
        for (int n2 = 0; n2 < 6; n2++)
#pragma unroll
            for (int ii = 0; ii < 12; ii++) ea[n2][ii] = 0.f;
        for (int k = 0; k < 96; k++) {
            float gk = sg[k];
            float wv[6];
#pragma unroll
            for (int n2 = 0; n2 < 6; n2++) {
                wv[n2] = W1[(bn + n2) * 96 + k] * gk;
                aa[n2] += wv[n2];
            }
#pragma unroll
            for (int ii = 0; ii < 12; ii += 2) {
                float2 dv = *(float2*)(D32 + k * 96 + bi + ii);
#pragma unroll
                for (int n2 = 0; n2 < 6; n2++) {
                    ea[n2][ii]     = fmaf(wv[n2], dv.x, ea[n2][ii]);
                    ea[n2][ii + 1] = fmaf(wv[n2], dv.y, ea[n2][ii + 1]);
                }
            }
        }
#pragma unroll
        for (int n2 = 0; n2 < 6; n2++)
#pragma unroll
            for (int ii = 0; ii < 12; ii++) {
                float v = ea[n2][ii] - aa[n2] * smv[bi + ii];   // fold -a m^T
                int off = (bn + n2) * STR_E + (bi + ii) * 2;
                *(__half*)(sm + OFF_EHI + off) = __float2half_rn(v);
            }
    }
    __syncthreads();

    // ========== STAGE 4: W2 f16 hi (overwrites D scratch) ==========
    for (int t = tid; t < 96 * 192; t += TPB) {
        int n = t / 192, i = t % 192;
        *(__half*)(sm + OFF_W2HI + n * STR_W2 + i * 2) = __float2half_rn(W2[t]);
    }
    __syncthreads();

    const uint32_t lrow = lane & 7;
    const uint32_t lkb  = (uint32_t)(lane >> 3) * 16;
    const uint32_t bEh  = sb + OFF_EHI  + lrow * STR_E  + lkb;
    const uint32_t bW2h = sb + OFF_W2HI + lrow * STR_W2 + lkb;

    const int ntiles = (rows + RPT - 1) / RPT;

    for (int tile = blockIdx.x; tile < ntiles; tile += gridDim.x) {
        const int r0 = tile * RPT + warp * 32 + gid;   // group rows: r0, r0+8, r0+16, r0+24
        const float* xr0 = x + (size_t)min(r0,      rows - 1) * NN;
        const float* xr1 = x + (size_t)min(r0 + 8,  rows - 1) * NN;
        const float* xr2 = x + (size_t)min(r0 + 16, rows - 1) * NN;
        const float* xr3 = x + (size_t)min(r0 + 24, rows - 1) * NN;

        // ===== load x (4 rows), build f16 A-fragments, accumulate LN1 stats =====
        uint32_t a2h[6][8];
        float s1_0 = 0.f, sq_0 = 0.f, sm_0 = 0.f;
        float s1_1 = 0.f, sq_1 = 0.f, sm_1 = 0.f;
        float s1_2 = 0.f, sq_2 = 0.f, sm_2 = 0.f;
        float s1_3 = 0.f, sq_3 = 0.f, sm_3 = 0.f;
#pragma unroll
        for (int ktp = 0; ktp < 3; ktp++) {
            int kb = 32 * ktp + 2 * tig;
#pragma unroll
            for (int p = 0; p < 4; p++) {
                float2 v0 = *(const float2*)(xr0 + kb + 8 * p);
                float2 v1 = *(const float2*)(xr1 + kb + 8 * p);
                float2 v2 = *(const float2*)(xr2 + kb + 8 * p);
                float2 v3 = *(const float2*)(xr3 + kb + 8 * p);
                float2 mv = *(const float2*)(smv + kb + 8 * p);
                s1_0 += v0.x + v0.y;
                sq_0 = fmaf(v0.x, v0.x, fmaf(v0.y, v0.y, sq_0));
                sm_0 = fmaf(v0.x, mv.x, fmaf(v0.y, mv.y, sm_0));
                s1_1 += v1.x + v1.y;
                sq_1 = fmaf(v1.x, v1.x, fmaf(v1.y, v1.y, sq_1));
                sm_1 = fmaf(v1.x, mv.x, fmaf(v1.y, mv.y, sm_1));
                s1_2 += v2.x + v2.y;
                sq_2 = fmaf(v2.x, v2.x, fmaf(v2.y, v2.y, sq_2));
                sm_2 = fmaf(v2.x, mv.x, fmaf(v2.y, mv.y, sm_2));
                s1_3 += v3.x + v3.y;
                sq_3 = fmaf(v3.x, v3.x, fmaf(v3.y, v3.y, sq_3));
                sm_3 = fmaf(v3.x, mv.x, fmaf(v3.y, mv.y, sm_3));
                int kk = 2 * ktp + (p >> 1);
                int of = (p & 1) * 2;
                a2h[kk][of]     = pk2(v0.x, v0.y);
                a2h[kk][of + 1] = pk2(v1.x, v1.y);
                a2h[kk][of + 4] = pk2(v2.x, v2.y);
                a2h[kk][of + 5] = pk2(v3.x, v3.y);
            }
        }
        s1_0 += __shfl_xor_sync(~0u, s1_0, 1); s1_0 += __shfl_xor_sync(~0u, s1_0, 2);
        sq_0 += __shfl_xor_sync(~0u, sq_0, 1); sq_0 += __shfl_xor_sync(~0u, sq_0, 2);
        sm_0 += __shfl_xor_sync(~0u, sm_0, 1); sm_0 += __shfl_xor_sync(~0u, sm_0, 2);
        s1_1 += __shfl_xor_sync(~0u, s1_1, 1); s1_1 += __shfl_xor_sync(~0u, s1_1, 2);
        sq_1 += __shfl_xor_sync(~0u, sq_1, 1); sq_1 += __shfl_xor_sync(~0u, sq_1, 2);
        sm_1 += __shfl_xor_sync(~0u, sm_1, 1); sm_1 += __shfl_xor_sync(~0u, sm_1, 2);
        s1_2 += __shfl_xor_sync(~0u, s1_2, 1); s1_2 += __shfl_xor_sync(~0u, s1_2, 2);
        sq_2 += __shfl_xor_sync(~0u, sq_2, 1); sq_2 += __shfl_xor_sync(~0u, sq_2, 2);
        sm_2 += __shfl_xor_sync(~0u, sm_2, 1); sm_2 += __shfl_xor_sync(~0u, sm_2, 2);
        s1_3 += __shfl_xor_sync(~0u, s1_3, 1); s1_3 += __shfl_xor_sync(~0u, s1_3, 2);
        sq_3 += __shfl_xor_sync(~0u, sq_3, 1); sq_3 += __shfl_xor_sync(~0u, sq_3, 2);
        sm_3 += __shfl_xor_sync(~0u, sm_3, 1); sm_3 += __shfl_xor_sync(~0u, sm_3, 2);
        // LN1 via DCT structure: var = 2*||x||^2 + (sum x)^2/48 - mu^2 ; mu = x.m
        float rs0 = rsqrtf(2.0f * sq_0 + s1_0 * s1_0 * (1.0f / 48.0f) - sm_0 * sm_0 + EPSV);
        float rs1 = rsqrtf(2.0f * sq_1 + s1_1 * s1_1 * (1.0f / 48.0f) - sm_1 * sm_1 + EPSV);
        float rs2 = rsqrtf(2.0f * sq_2 + s1_2 * s1_2 * (1.0f / 48.0f) - sm_2 * sm_2 + EPSV);
        float rs3 = rsqrtf(2.0f * sq_3 + s1_3 * s1_3 * (1.0f / 48.0f) - sm_3 * sm_3 + EPSV);

        // ========== Fused GEMM-E' -> (rs*z+b, relu) -> GEMM3, M=32 ==========
        float sfr[12][8];
#pragma unroll
        for (int i = 0; i < 12; i++)
#pragma unroll
            for (int q = 0; q < 8; q++) sfr[i][q] = 0.f;

#pragma unroll
        for (int g = 0; g < 6; g++) {
            float ac2[4][8];
#pragma unroll
            for (int j = 0; j < 4; j++)
#pragma unroll
                for (int q = 0; q < 8; q++) ac2[j][q] = 0.f;
#pragma unroll
            for (int ktp = 0; ktp < 3; ktp++) {
                uint32_t wh[4][4];
#pragma unroll
                for (int j = 0; j < 4; j++) {
                    int nt = 4 * g + j;
                    LDSM4(wh[j][0], wh[j][1], wh[j][2], wh[j][3], bEh + nt * (8 * STR_E) + ktp * 64);
                }
#pragma unroll
                for (int j = 0; j < 4; j++) MMA(ac2[j],     a2h[2*ktp],         wh[j][0], wh[j][1]);
#pragma unroll
                for (int j = 0; j < 4; j++) MMA(ac2[j] + 4, a2h[2*ktp] + 4,     wh[j][0], wh[j][1]);
#pragma unroll
                for (int j = 0; j < 4; j++) MMA(ac2[j],     a2h[2*ktp + 1],     wh[j][2], wh[j][3]);
#pragma unroll
                for (int j = 0; j < 4; j++) MMA(ac2[j] + 4, a2h[2*ktp + 1] + 4, wh[j][2], wh[j][3]);
            }
            // rs*z + b, relu, pack -> GEMM3 k32 A-fragments per row group
            uint32_t hA0[4], hA1[4], hB0[4], hB1[4];
#pragma unroll
            for (int j = 0; j < 4; j++) {
                int nt = 4 * g + j;
                float2 bv = *(const float2*)(sb2 + 8 * nt + 2 * tig);
                float eA0 = fmaxf(fmaf(rs0, ac2[j][0], bv.x), 0.f);
                float eA1 = fmaxf(fmaf(rs0, ac2[j][1], bv.y), 0.f);
                float eA2 = fmaxf(fmaf(rs1, ac2[j][2], bv.x), 0.f);
                float eA3 = fmaxf(fmaf(rs1, ac2[j][3], bv.y), 0.f);
                float eB0 = fmaxf(fmaf(rs2, ac2[j][4], bv.x), 0.f);
                float eB1 = fmaxf(fmaf(rs2, ac2[j][5], bv.y), 0.f);
                float eB2 = fmaxf(fmaf(rs3, ac2[j][6], bv.x), 0.f);
                float eB3 = fmaxf(fmaf(rs3, ac2[j][7], bv.y), 0.f);
                if (j < 2) {
                    hA0[2 * j]     = pk2(eA0, eA1);
                    hA0[2 * j + 1] = pk2(eA2, eA3);
                    hB0[2 * j]     = pk2(eB0, eB1);
                    hB0[2 * j + 1] = pk2(eB2, eB3);
                } else {
                    hA1[2 * (j - 2)]     = pk2(eA0, eA1);
                    hA1[2 * (j - 2) + 1] = pk2(eA2, eA3);
                    hB1[2 * (j - 2)]     = pk2(eB0, eB1);
                    hB1[2 * (j - 2) + 1] = pk2(eB2, eB3);
                }
            }

            // GEMM3 k32 update, both row groups reuse each weight fragment
#pragma unroll
            for (int jb = 0; jb < 3; jb++) {
                uint32_t vh[4][4];
#pragma unroll
                for (int j = 0; j < 4; j++) {
                    int nt = 4 * jb + j;
                    LDSM4(vh[j][0], vh[j][1], vh[j][2], vh[j][3], bW2h + nt * (8 * STR_W2) + g * 64);
                }
#pragma unroll
                for (int j = 0; j < 4; j++) MMA(sfr[4*jb+j],     hA0, vh[j][0], vh[j][1]);
#pragma unroll
                for (int j = 0; j < 4; j++) MMA(sfr[4*jb+j] + 4, hB0, vh[j][0], vh[j][1]);
#pragma unroll
                for (int j = 0; j < 4; j++) MMA(sfr[4*jb+j],     hA1, vh[j][2], vh[j][3]);
#pragma unroll
                for (int j = 0; j < 4; j++) MMA(sfr[4*jb+j] + 4, hB1, vh[j][2], vh[j][3]);
            }
        }

        // ================= sigmoid + LayerNorm 2 + output (4 rows) =================
#pragma unroll
        for (int nt = 0; nt < 12; nt++)
#pragma unroll
            for (int q = 0; q < 8; q++)
                sfr[nt][q] = fast_sigmoid(sfr[nt][q]);

        float t0 = 0.f, t1 = 0.f, t2 = 0.f, t3 = 0.f;
#pragma unroll
        for (int nt = 0; nt < 12; nt++) {
            t0 += sfr[nt][0] + sfr[nt][1]; t1 += sfr[nt][2] + sfr[nt][3];
            t2 += sfr[nt][4] + sfr[nt][5]; t3 += sfr[nt][6] + sfr[nt][7];
        }
        t0 += __shfl_xor_sync(~0u, t0, 1); t0 += __shfl_xor_sync(~0u, t0, 2);
        t1 += __shfl_xor_sync(~0u, t1, 1); t1 += __shfl_xor_sync(~0u, t1, 2);
        t2 += __shfl_xor_sync(~0u, t2, 1); t2 += __shfl_xor_sync(~0u, t2, 2);
        t3 += __shfl_xor_sync(~0u, t3, 1); t3 += __shfl_xor_sync(~0u, t3, 2);
        float m0 = t0 * (1.f/96.f), m1 = t1 * (1.f/96.f), m2 = t2 * (1.f/96.f), m3 = t3 * (1.f/96.f);
        float p0 = 0.f, p1 = 0.f, p2 = 0.f, p3 = 0.f;
#pragma unroll
        for (int nt = 0; nt < 12; nt++) {
            float d;
            d = sfr[nt][0] - m0; p0 = fmaf(d, d, p0);
            d = sfr[nt][1] - m0; p0 = fmaf(d, d, p0);
            d = sfr[nt][2] - m1; p1 = fmaf(d, d, p1);
            d = sfr[nt][3] - m1; p1 = fmaf(d, d, p1);
            d = sfr[nt][4] - m2; p2 = fmaf(d, d, p2);
            d = sfr[nt][5] - m2; p2 = fmaf(d, d, p2);
            d = sfr[nt][6] - m3; p3 = fmaf(d, d, p3);
            d = sfr[nt][7] - m3; p3 = fmaf(d, d, p3);
        }
        p0 += __shfl_xor_sync(~0u, p0, 1); p0 += __shfl_xor_sync(~0u, p0, 2);
        p1 += __shfl_xor_sync(~0u, p1, 1); p1 += __shfl_xor_sync(~0u, p1, 2);
        p2 += __shfl_xor_sync(~0u, p2, 1); p2 += __shfl_xor_sync(~0u, p2, 2);
        p3 += __shfl_xor_sync(~0u, p3, 1); p3 += __shfl_xor_sync(~0u, p3, 2);
        float z0 = rsqrtf(p0 * (1.f/96.f) + EPSV);
        float z1 = rsqrtf(p1 * (1.f/96.f) + EPSV);
        float z2 = rsqrtf(p2 * (1.f/96.f) + EPSV);
        float z3 = rsqrtf(p3 * (1.f/96.f) + EPSV);

        // out = x * (LN2(s)*gamma + beta); x taken from the f16 A-fragments (a2h)
#pragma unroll
        for (int nt = 0; nt < 12; nt++) {
            int col = 8 * nt + 2 * tig;
            float2 gv = *(const float2*)(sg  + col);
            float2 bv = *(const float2*)(sbt + col);
            int kk = nt >> 1, of = (nt & 1) * 2;
            int rr[4] = { r0, r0 + 8, r0 + 16, r0 + 24 };
            float mm[4] = { m0, m1, m2, m3 };
            float zz[4] = { z0, z1, z2, z3 };
#pragma unroll
            for (int gq = 0; gq < 4; gq++) {
                if (rr[gq] < rows) {
                    float wa = fmaf((sfr[nt][2 * gq]     - mm[gq]) * zz[gq], gv.x, bv.x);
                    float wb = fmaf((sfr[nt][2 * gq + 1] - mm[gq]) * zz[gq], gv.y, bv.y);
                    __half2 xh = *(__half2*)&a2h[kk][of + (gq & 1) + (gq >> 1) * 4];
                    float2 xv = __half22float2(xh);
                    float2 o; o.x = xv.x * wa; o.y = xv.y * wb;
                    *(float2*)(out + (size_t)rr[gq] * NN + col) = o;
                }
            }
        }
    }
}

extern "C" void kernel_launch(void* const* d_in, const int* in_sizes, int n_in,
                              void* d_out, int out_size) {
    const float* x     = (const float*)d_in[0];
    const float* W1    = (const float*)d_in[1];
    const float* W2    = (const float*)d_in[2];
    const float* gamma = (const float*)d_in[3];
    const float* beta  = (const float*)d_in[4];
    float* out = (float*)d_out;

    int rows = in_sizes[0] / NN;

    cudaFuncSetAttribute(fused_mma_kernel, cudaFuncAttributeMaxDynamicSharedMemorySize, SMEM_TOTAL);
    fused_mma_kernel<<<152, TPB, SMEM_TOTAL>>>(x, W1, W2, gamma, beta, out, rows);
}

// round 16
// speedup vs baseline: 2.0967x; 1.0667x over previous
#include <cuda_runtime.h>
#include <cuda_fp16.h>
#include <math.h>
#include <stdint.h>

#define NN   96
#define HH   192
#define TPB  256
#define RPT  (8 * 32)    // 8 warps x 32 rows
#define EPSV 1e-6f

// ---------------- smem layout (bytes) ----------------
#define OFF_G     0                       // float gamma[96]
#define OFF_B     384                     // float beta[96]
#define OFF_M     768                     // float m[96]  (column means of D)
#define OFF_B2    1152                    // float b[192] (W1 @ beta)
#define OFF_EHI   1920                    // E' = (W1*gamma)@D - a m^T : 192 x 96, f16
#define STR_E     208
#define SZ_E      (192 * 208)             // 39936
#define OFF_W2HI  (OFF_EHI + SZ_E)        // 41856 ; also fp32 D scratch during staging
#define STR_W2    400
#define SZ_W2     (96 * 400)              // 38400
#define SMEM_TOTAL (OFF_W2HI + SZ_W2)     // 80256

__device__ __forceinline__ uint32_t smem_u32(const void* p) {
    uint32_t a;
    asm("{ .reg .u64 t; cvta.to.shared.u64 t, %1; cvt.u32.u64 %0, t; }" : "=r"(a) : "l"(p));
    return a;
}

#define LDSM4(d0, d1, d2, d3, a) \
    asm volatile("ldmatrix.sync.aligned.m8n8.x4.shared.b16 {%0,%1,%2,%3}, [%4];" \
        : "=r"(d0), "=r"(d1), "=r"(d2), "=r"(d3) : "r"(a))

#define MMA(ac, A, b0, b1) \
    asm volatile("mma.sync.aligned.m16n8k16.row.col.f32.f16.f16.f32 " \
        "{%0,%1,%2,%3}, {%4,%5,%6,%7}, {%8,%9}, {%0,%1,%2,%3};" \
        : "+f"((ac)[0]), "+f"((ac)[1]), "+f"((ac)[2]), "+f"((ac)[3]) \
        : "r"((A)[0]), "r"((A)[1]), "r"((A)[2]), "r"((A)[3]), "r"(b0), "r"(b1))

#define PREFETCH_L2(p) asm volatile("prefetch.global.L2 [%0];" :: "l"(p))

__device__ __forceinline__ uint32_t pk2(float a, float b) {
    __half2 h = __floats2half2_rn(a, b);
    return *(uint32_t*)&h;
}

__device__ __forceinline__ float fast_sigmoid(float v) {
    float t;
    asm("tanh.approx.f32 %0, %1;" : "=f"(t) : "f"(v * 0.5f));
    return fmaf(t, 0.5f, 0.5f);
}

extern __shared__ char sm[];

__global__ void __launch_bounds__(TPB, 1)
fused_mma_kernel(const float* __restrict__ x,
                 const float* __restrict__ W1,
                 const float* __restrict__ W2,
                 const float* __restrict__ gamma,
                 const float* __restrict__ beta,
                 float* __restrict__ out,
                 int rows) {
    const int tid  = threadIdx.x;
    const int lane = tid & 31;
    const int warp = tid >> 5;
    const int gid  = lane >> 2;
    const int tig  = lane & 3;
    const uint32_t sb = smem_u32(sm);

    float* sg  = (float*)(sm + OFF_G);
    float* sbt = (float*)(sm + OFF_B);
    float* smv = (float*)(sm + OFF_M);
    float* sb2 = (float*)(sm + OFF_B2);
    float* D32 = (float*)(sm + OFF_W2HI);   // staging scratch

    // ========== STAGE 1: gamma/beta + fp32 DCT matrix into scratch ==========
    if (tid < 96) { sg[tid] = gamma[tid]; sbt[tid] = beta[tid]; }
    const float PI192 = 0.016362461737446838f;
    for (int t = tid; t < 96 * 96; t += TPB) {
        int k = t / 96, i = t % 96;
        int mm = ((2 * i + 1) * k) % 384;
        D32[t] = 2.0f * cosf(PI192 * (float)mm);
    }
    __syncthreads();

    // ========== STAGE 2: m (col means of D), b = W1@beta ==========
    if (tid < 96) {
        float s = 0.f;
        for (int k = 0; k < 96; k++) s += D32[k * 96 + tid];
        smv[tid] = s * (1.0f / 96.0f);
    }
    if (tid < 192) {
        float bbv = 0.f;
        for (int k = 0; k < 96; k++) bbv = fmaf(W1[tid * 96 + k], sbt[k], bbv);
        sb2[tid] = bbv;
    }
    __syncthreads();

    // ========== STAGE 3: E' = (W1*gamma)@D - a m^T (f16 hi only) ==========
    {
        int bn = (tid >> 3) * 6;       // n-block 0..186
        int bi = (tid & 7) * 12;       // i-block 0..84
        float ea[6][12];
        float aa[6] = {0.f, 0.f, 0.f, 0.f, 0.f, 0.f};
#pragma unroll
        for (int n2 = 0; n2 < 6; n2++)
#pragma unroll
            for (int ii = 0; ii < 12; ii++) ea[n2][ii] = 0.f;
        for (int k = 0; k < 96; k++) {
            float gk = sg[k];
            float wv[6];
#pragma unroll
            for (int n2 = 0; n2 < 6; n2++) {
                wv[n2] = W1[(bn + n2) * 96 + k] * gk;
                aa[n2] += wv[n2];
            }
#pragma unroll
            for (int ii = 0; ii < 12; ii += 2) {
                float2 dv = *(float2*)(D32 + k * 96 + bi + ii);
#pragma unroll
                for (int n2 = 0; n2 < 6; n2++) {
                    ea[n2][ii]     = fmaf(wv[n2], dv.x, ea[n2][ii]);
                    ea[n2][ii + 1] = fmaf(wv[n2], dv.y, ea[n2][ii + 1]);
                }
            }
        }
#pragma unroll
        for (int n2 = 0; n2 < 6; n2++)
#pragma unroll
            for (int ii = 0; ii < 12; ii++) {
                float v = ea[n2][ii] - aa[n2] * smv[bi + ii];   // fold -a m^T
                int off = (bn + n2) * STR_E + (bi + ii) * 2;
                *(__half*)(sm + OFF_EHI + off) = __float2half_rn(v);
            }
    }
    __syncthreads();

    // ========== STAGE 4: W2 f16 hi (overwrites D scratch) ==========
    for (int t = tid; t < 96 * 192; t += TPB) {
        int n = t / 192, i = t % 192;
        *(__half*)(sm + OFF_W2HI + n * STR_W2 + i * 2) = __float2half_rn(W2[t]);
    }
    __syncthreads();

    const uint32_t lrow = lane & 7;
    const uint32_t lkb  = (uint32_t)(lane >> 3) * 16;
    const uint32_t bEh  = sb + OFF_EHI  + lrow * STR_E  + lkb;
    const uint32_t bW2h = sb + OFF_W2HI + lrow * STR_W2 + lkb;

    const int ntiles = (rows + RPT - 1) / RPT;

    for (int tile = blockIdx.x; tile < ntiles; tile += gridDim.x) {
        const int r0 = tile * RPT + warp * 32 + gid;   // group rows: r0, r0+8, r0+16, r0+24
        const float* xr0 = x + (size_t)min(r0,      rows - 1) * NN;
        const float* xr1 = x + (size_t)min(r0 + 8,  rows - 1) * NN;
        const float* xr2 = x + (size_t)min(r0 + 16, rows - 1) * NN;
        const float* xr3 = x + (size_t)min(r0 + 24, rows - 1) * NN;

        // ===== load x (4 rows), build f16 A-fragments, accumulate LN1 stats =====
        uint32_t a2h[6][8];
        float s1_0 = 0.f, sq_0 = 0.f, sm_0 = 0.f;
        float s1_1 = 0.f, sq_1 = 0.f, sm_1 = 0.f;
        float s1_2 = 0.f, sq_2 = 0.f, sm_2 = 0.f;
        float s1_3 = 0.f, sq_3 = 0.f, sm_3 = 0.f;
#pragma unroll
        for (int ktp = 0; ktp < 3; ktp++) {
            int kb = 32 * ktp + 2 * tig;
#pragma unroll
            for (int p = 0; p < 4; p++) {
                float2 v0 = *(const float2*)(xr0 + kb + 8 * p);
                float2 v1 = *(const float2*)(xr1 + kb + 8 * p);
                float2 v2 = *(const float2*)(xr2 + kb + 8 * p);
                float2 v3 = *(const float2*)(xr3 + kb + 8 * p);
                float2 mv = *(const float2*)(smv + kb + 8 * p);
                s1_0 += v0.x + v0.y;
                sq_0 = fmaf(v0.x, v0.x, fmaf(v0.y, v0.y, sq_0));
                sm_0 = fmaf(v0.x, mv.x, fmaf(v0.y, mv.y, sm_0));
                s1_1 += v1.x + v1.y;
                sq_1 = fmaf(v1.x, v1.x, fmaf(v1.y, v1.y, sq_1));
                sm_1 = fmaf(v1.x, mv.x, fmaf(v1.y, mv.y, sm_1));
                s1_2 += v2.x + v2.y;
                sq_2 = fmaf(v2.x, v2.x, fmaf(v2.y, v2.y, sq_2));
                sm_2 = fmaf(v2.x, mv.x, fmaf(v2.y, mv.y, sm_2));
                s1_3 += v3.x + v3.y;
                sq_3 = fmaf(v3.x, v3.x, fmaf(v3.y, v3.y, sq_3));
                sm_3 = fmaf(v3.x, mv.x, fmaf(v3.y, mv.y, sm_3));
                int kk = 2 * ktp + (p >> 1);
                int of = (p & 1) * 2;
                a2h[kk][of]     = pk2(v0.x, v0.y);
                a2h[kk][of + 1] = pk2(v1.x, v1.y);
                a2h[kk][of + 4] = pk2(v2.x, v2.y);
                a2h[kk][of + 5] = pk2(v3.x, v3.y);
            }
        }
        s1_0 += __shfl_xor_sync(~0u, s1_0, 1); s1_0 += __shfl_xor_sync(~0u, s1_0, 2);
        sq_0 += __shfl_xor_sync(~0u, sq_0, 1); sq_0 += __shfl_xor_sync(~0u, sq_0, 2);
        sm_0 += __shfl_xor_sync(~0u, sm_0, 1); sm_0 += __shfl_xor_sync(~0u, sm_0, 2);
        s1_1 += __shfl_xor_sync(~0u, s1_1, 1); s1_1 += __shfl_xor_sync(~0u, s1_1, 2);
        sq_1 += __shfl_xor_sync(~0u, sq_1, 1); sq_1 += __shfl_xor_sync(~0u, sq_1, 2);
        sm_1 += __shfl_xor_sync(~0u, sm_1, 1); sm_1 += __shfl_xor_sync(~0u, sm_1, 2);
        s1_2 += __shfl_xor_sync(~0u, s1_2, 1); s1_2 += __shfl_xor_sync(~0u, s1_2, 2);
        sq_2 += __shfl_xor_sync(~0u, sq_2, 1); sq_2 += __shfl_xor_sync(~0u, sq_2, 2);
        sm_2 += __shfl_xor_sync(~0u, sm_2, 1); sm_2 += __shfl_xor_sync(~0u, sm_2, 2);
        s1_3 += __shfl_xor_sync(~0u, s1_3, 1); s1_3 += __shfl_xor_sync(~0u, s1_3, 2);
        sq_3 += __shfl_xor_sync(~0u, sq_3, 1); sq_3 += __shfl_xor_sync(~0u, sq_3, 2);
        sm_3 += __shfl_xor_sync(~0u, sm_3, 1); sm_3 += __shfl_xor_sync(~0u, sm_3, 2);
        // LN1 via DCT structure: var = 2*||x||^2 + (sum x)^2/48 - mu^2 ; mu = x.m
        float rs0 = rsqrtf(2.0f * sq_0 + s1_0 * s1_0 * (1.0f / 48.0f) - sm_0 * sm_0 + EPSV);
        float rs1 = rsqrtf(2.0f * sq_1 + s1_1 * s1_1 * (1.0f / 48.0f) - sm_1 * sm_1 + EPSV);
        float rs2 = rsqrtf(2.0f * sq_2 + s1_2 * s1_2 * (1.0f / 48.0f) - sm_2 * sm_2 + EPSV);
        float rs3 = rsqrtf(2.0f * sq_3 + s1_3 * s1_3 * (1.0f / 48.0f) - sm_3 * sm_3 + EPSV);

        // ---- L2 prefetch of next tile's x rows (32 rows x 3 lines per warp) ----
        {
            int nt2 = tile + gridDim.x;
            if (nt2 < ntiles) {
                int pr = nt2 * RPT + warp * 32 + lane;
                const float* prow = x + (size_t)min(pr, rows - 1) * NN;
                PREFETCH_L2(prow);
                PREFETCH_L2(prow + 32);
                PREFETCH_L2(prow + 64);
            }
        }

        // ========== Fused GEMM-E' -> (rs*z+b, relu) -> GEMM3, M=32 ==========
        float sfr[12][8];
#pragma unroll
        for (int i = 0; i < 12; i++)
#pragma unroll
            for (int q = 0; q < 8; q++) sfr[i][q] = 0.f;

#pragma unroll
        for (int g = 0; g < 6; g++) {
            float ac2[4][8];
#pragma unroll
            for (int j = 0; j < 4; j++)
#pragma unroll
                for (int q = 0; q < 8; q++) ac2[j][q] = 0.f;
#pragma unroll
            for (int ktp = 0; ktp < 3; ktp++) {
                uint32_t wh[4][4];
#pragma unroll
                for (int j = 0; j < 4; j++) {
                    int nt = 4 * g + j;
                    LDSM4(wh[j][0], wh[j][1], wh[j][2], wh[j][3], bEh + nt * (8 * STR_E) + ktp * 64);
                }
#pragma unroll
                for (int j = 0; j < 4; j++) MMA(ac2[j],     a2h[2*ktp],         wh[j][0], wh[j][1]);
#pragma unroll
                for (int j = 0; j < 4; j++) MMA(ac2[j] + 4, a2h[2*ktp] + 4,     wh[j][0], wh[j][1]);
#pragma unroll
                for (int j = 0; j < 4; j++) MMA(ac2[j],     a2h[2*ktp + 1],     wh[j][2], wh[j][3]);
#pragma unroll
                for (int j = 0; j < 4; j++) MMA(ac2[j] + 4, a2h[2*ktp + 1] + 4, wh[j][2], wh[j][3]);
            }
            // rs*z + b, relu, pack -> GEMM3 k32 A-fragments per row group
            uint32_t hA0[4], hA1[4], hB0[4], hB1[4];
#pragma unroll
            for (int j = 0; j < 4; j++) {
                int nt = 4 * g + j;
                float2 bv = *(const float2*)(sb2 + 8 * nt + 2 * tig);
                float eA0 = fmaxf(fmaf(rs0, ac2[j][0], bv.x), 0.f);
                float eA1 = fmaxf(fmaf(rs0, ac2[j][1], bv.y), 0.f);
                float eA2 = fmaxf(fmaf(rs1, ac2[j][2], bv.x), 0.f);
                float eA3 = fmaxf(fmaf(rs1, ac2[j][3], bv.y), 0.f);
                float eB0 = fmaxf(fmaf(rs2, ac2[j][4], bv.x), 0.f);
                float eB1 = fmaxf(fmaf(rs2, ac2[j][5], bv.y), 0.f);
                float eB2 = fmaxf(fmaf(rs3, ac2[j][6], bv.x), 0.f);
                float eB3 = fmaxf(fmaf(rs3, ac2[j][7], bv.y), 0.f);
                if (j < 2) {
                    hA0[2 * j]     = pk2(eA0, eA1);
                    hA0[2 * j + 1] = pk2(eA2, eA3);
                    hB0[2 * j]     = pk2(eB0, eB1);
                    hB0[2 * j + 1] = pk2(eB2, eB3);
                } else {
                    hA1[2 * (j - 2)]     = pk2(eA0, eA1);
                    hA1[2 * (j - 2) + 1] = pk2(eA2, eA3);
                    hB1[2 * (j - 2)]     = pk2(eB0, eB1);
                    hB1[2 * (j - 2) + 1] = pk2(eB2, eB3);
                }
            }

            // GEMM3 k32 update, both row groups reuse each weight fragment
#pragma unroll
            for (int jb = 0; jb < 3; jb++) {
                uint32_t vh[4][4];
#pragma unroll
                for (int j = 0; j < 4; j++) {
                    int nt = 4 * jb + j;
                    LDSM4(vh[j][0], vh[j][1], vh[j][2], vh[j][3], bW2h + nt * (8 * STR_W2) + g * 64);
                }
#pragma unroll
                for (int j = 0; j < 4; j++) MMA(sfr[4*jb+j],     hA0, vh[j][0], vh[j][1]);
#pragma unroll
                for (int j = 0; j < 4; j++) MMA(sfr[4*jb+j] + 4, hB0, vh[j][0], vh[j][1]);
#pragma unroll
                for (int j = 0; j < 4; j++) MMA(sfr[4*jb+j],     hA1, vh[j][2], vh[j][3]);
#pragma unroll
                for (int j = 0; j < 4; j++) MMA(sfr[4*jb+j] + 4, hB1, vh[j][2], vh[j][3]);
            }
        }

        // ======== sigmoid + LayerNorm 2 (single-pass: sum & sumsq) + output ========
        float t0 = 0.f, t1 = 0.f, t2 = 0.f, t3 = 0.f;
        float u0 = 0.f, u1 = 0.f, u2 = 0.f, u3 = 0.f;
#pragma unroll
        for (int nt = 0; nt < 12; nt++) {
            float a = fast_sigmoid(sfr[nt][0]);
            float b = fast_sigmoid(sfr[nt][1]);
            float c = fast_sigmoid(sfr[nt][2]);
            float d = fast_sigmoid(sfr[nt][3]);
            float e = fast_sigmoid(sfr[nt][4]);
            float f = fast_sigmoid(sfr[nt][5]);
            float g2 = fast_sigmoid(sfr[nt][6]);
            float h2 = fast_sigmoid(sfr[nt][7]);
            sfr[nt][0] = a; sfr[nt][1] = b; sfr[nt][2] = c; sfr[nt][3] = d;
            sfr[nt][4] = e; sfr[nt][5] = f; sfr[nt][6] = g2; sfr[nt][7] = h2;
            t0 += a + b; u0 = fmaf(a, a, fmaf(b, b, u0));
            t1 += c + d; u1 = fmaf(c, c, fmaf(d, d, u1));
            t2 += e + f; u2 = fmaf(e, e, fmaf(f, f, u2));
            t3 += g2 + h2; u3 = fmaf(g2, g2, fmaf(h2, h2, u3));
        }
        t0 += __shfl_xor_sync(~0u, t0, 1); t0 += __shfl_xor_sync(~0u, t0, 2);
        u0 += __shfl_xor_sync(~0u, u0, 1); u0 += __shfl_xor_sync(~0u, u0, 2);
        t1 += __shfl_xor_sync(~0u, t1, 1); t1 += __shfl_xor_sync(~0u, t1, 2);
        u1 += __shfl_xor_sync(~0u, u1, 1); u1 += __shfl_xor_sync(~0u, u1, 2);
        t2 += __shfl_xor_sync(~0u, t2, 1); t2 += __shfl_xor_sync(~0u, t2, 2);
        u2 += __shfl_xor_sync(~0u, u2, 1); u2 += __shfl_xor_sync(~0u, u2, 2);
        t3 += __shfl_xor_sync(~0u, t3, 1); t3 += __shfl_xor_sync(~0u, t3, 2);
        u3 += __shfl_xor_sync(~0u, u3, 1); u3 += __shfl_xor_sync(~0u, u3, 2);
        float m0 = t0 * (1.f/96.f), m1 = t1 * (1.f/96.f), m2 = t2 * (1.f/96.f), m3 = t3 * (1.f/96.f);
        float z0 = rsqrtf(fmaf(-m0, m0, u0 * (1.f/96.f)) + EPSV);
        float z1 = rsqrtf(fmaf(-m1, m1, u1 * (1.f/96.f)) + EPSV);
        float z2 = rsqrtf(fmaf(-m2, m2, u2 * (1.f/96.f)) + EPSV);
        float z3 = rsqrtf(fmaf(-m3, m3, u3 * (1.f/96.f)) + EPSV);

        // out = x * (LN2(s)*gamma + beta); x taken from the f16 A-fragments (a2h)
#pragma unroll
        for (int nt = 0; nt < 12; nt++) {
            int col = 8 * nt + 2 * tig;
            float2 gv = *(const float2*)(sg  + col);
            float2 bv = *(const float2*)(sbt + col);
            int kk = nt >> 1, of = (nt & 1) * 2;
            int rr[4] = { r0, r0 + 8, r0 + 16, r0 + 24 };
            float mm[4] = { m0, m1, m2, m3 };
            float zz[4] = { z0, z1, z2, z3 };
#pragma unroll
            for (int gq = 0; gq < 4; gq++) {
                if (rr[gq] < rows) {
                    float wa = fmaf((sfr[nt][2 * gq]     - mm[gq]) * zz[gq], gv.x, bv.x);
                    float wb = fmaf((sfr[nt][2 * gq + 1] - mm[gq]) * zz[gq], gv.y, bv.y);
                    __half2 xh = *(__half2*)&a2h[kk][of + (gq & 1) + (gq >> 1) * 4];
                    float2 xv = __half22float2(xh);
                    float2 o; o.x = xv.x * wa; o.y = xv.y * wb;
                    *(float2*)(out + (size_t)rr[gq] * NN + col) = o;
                }
            }
        }
    }
}

extern "C" void kernel_launch(void* const* d_in, const int* in_sizes, int n_in,
                              void* d_out, int out_size) {
    const float* x     = (const float*)d_in[0];
    const float* W1    = (const float*)d_in[1];
    const float* W2    = (const float*)d_in[2];
    const float* gamma = (const float*)d_in[3];
    const float* beta  = (const float*)d_in[4];
    float* out = (float*)d_out;

    int rows = in_sizes[0] / NN;

    cudaFuncSetAttribute(fused_mma_kernel, cudaFuncAttributeMaxDynamicSharedMemorySize, SMEM_TOTAL);
    fused_mma_kernel<<<152, TPB, SMEM_TOTAL>>>(x, W1, W2, gamma, beta, out, rows);
}